// round 2
// baseline (speedup 1.0000x reference)
#include <cuda_runtime.h>
#include <cuda_bf16.h>

// ---------------------------------------------------------------------------
// LocalGlobalCrossAttentionModel
//
// Key insight: softmax over an axis of size 1 is identically 1.0, so the
// attention output is just v (global branch) — the entire shapelet/local
// branch (q, k, feat, local layernorm, 16.7 GFLOP of correlation conv) is
// dead code. Only the CNN/global branch contributes to the output:
//   x -> conv1(16,1,3,5) pad(1,2) -> relu -> maxpool(w/2)
//     -> conv2(32,16,3,5) pad(1,2) -> relu -> maxpool(w/2)
//     -> mean(h,w) -> relu(g@w_glob+b) -> layernorm -> v -> out_w -> mlp
// ---------------------------------------------------------------------------

#define B_  64
#define H_  8
#define W1_ 2048   // conv1 width
#define W1P 1024   // after pool1
#define W2P 512    // after pool2
#define C1  16
#define C2  32

// Scratch (device globals; no allocation allowed)
__device__ float g_h1[B_ * C1 * H_ * W1P];       // pooled conv1 output, 33.5 MB
__device__ float g_part[B_ * C2 * 32];           // per-(b,co,wtile) partial sums

// ---------------------------------------------------------------------------
// Kernel 1: conv1 (1->16 ch, 3x5, pad 1,2) + relu + maxpool over width pairs
// Block: fixed (b, co, h), 256 threads cover 256 pooled w positions.
// ---------------------------------------------------------------------------
__global__ __launch_bounds__(256) void conv1_pool_kernel(
    const float* __restrict__ x,
    const float* __restrict__ w1,
    const float* __restrict__ b1)
{
    int bz = blockIdx.z;
    int b  = bz >> 4;
    int co = bz & 15;
    int h  = blockIdx.y;
    int wp0 = blockIdx.x * 256;

    __shared__ __align__(16) float xs[3][520];

    float wgt[15];
#pragma unroll
    for (int i = 0; i < 15; i++) wgt[i] = __ldg(&w1[co * 15 + i]);
    float bias = __ldg(&b1[co]);

    // load rows h-1..h+1, cols 2*wp0-2 .. 2*wp0+513 (zero padded)
    int c0 = 2 * wp0 - 2;
    for (int idx = threadIdx.x; idx < 3 * 516; idx += 256) {
        int r = idx / 516;
        int j = idx - r * 516;
        int hr = h - 1 + r;
        int c  = c0 + j;
        float v = 0.f;
        if (hr >= 0 && hr < H_ && c >= 0 && c < W1_)
            v = x[(b * H_ + hr) * W1_ + c];
        xs[r][j] = v;
    }
    __syncthreads();

    int t = threadIdx.x;
    float v0 = bias, v1 = bias;
#pragma unroll
    for (int kh = 0; kh < 3; kh++) {
#pragma unroll
        for (int kw = 0; kw < 5; kw++) {
            float w = wgt[kh * 5 + kw];
            v0 += w * xs[kh][2 * t + kw];
            v1 += w * xs[kh][2 * t + 1 + kw];
        }
    }
    float m = fmaxf(fmaxf(v0, v1), 0.f);
    g_h1[((b * C1 + co) * H_ + h) * W1P + wp0 + t] = m;
}

// ---------------------------------------------------------------------------
// Kernel 2: conv2 (16->32 ch, 3x5, pad 1,2) + relu + maxpool + partial mean.
// Grid: (wtile=32, b=64). Block 256 threads = (co in 0..31) x (h in 0..7).
// Each thread computes 32 conv positions (16 pooled) for its (co,h),
// accumulating in registers; input rows cached in registers via LDS.128
// (warp-broadcast), weights in smem transposed [ci][k][co] (conflict-free).
// This makes FFMA issue the binding constraint (~2 instr/cyc/SM).
// ---------------------------------------------------------------------------
__global__ __launch_bounds__(256) void conv2_pool_kernel(
    const float* __restrict__ w2,
    const float* __restrict__ b2)
{
    int b  = blockIdx.y;
    int wt = blockIdx.x;           // 32 tiles of 16 pooled outputs
    int tid = threadIdx.x;
    int co = tid & 31;
    int h  = tid >> 5;

    __shared__ __align__(16) float wt_s[16][15][32];  // [ci][kh*5+kw][co]
    __shared__ __align__(16) float in_s[16][10][40];  // [ci][h_padded][col]
    __shared__ float red[8][33];

    // weights: global layout w2[(co*16+ci)*15 + k]
    for (int idx = tid; idx < 16 * 15 * 32; idx += 256) {
        int c_ = idx & 31;
        int rest = idx >> 5;
        int k  = rest % 15;
        int ci = rest / 15;
        wt_s[ci][k][c_] = w2[(c_ * 16 + ci) * 15 + k];
    }
    // input tile: rows r=0..9 -> input row r-1 (zero pad), cols j=0..35 -> wt*32-2+j
    int cbase = wt * 32 - 2;
    for (int idx = tid; idx < 16 * 10 * 36; idx += 256) {
        int j = idx % 36;
        int rest = idx / 36;
        int r  = rest % 10;
        int ci = rest / 10;
        int hr = r - 1;
        int c  = cbase + j;
        float v = 0.f;
        if (hr >= 0 && hr < H_ && c >= 0 && c < W1P)
            v = g_h1[((b * C1 + ci) * H_ + hr) * W1P + c];
        in_s[ci][r][j] = v;
    }
    __syncthreads();

    float bias = __ldg(&b2[co]);
    float acc[32];
#pragma unroll
    for (int w = 0; w < 32; w++) acc[w] = bias;

    for (int ci = 0; ci < 16; ci++) {
#pragma unroll
        for (int kh = 0; kh < 3; kh++) {
            float r[36];
            const float4* rp = reinterpret_cast<const float4*>(&in_s[ci][h + kh][0]);
#pragma unroll
            for (int j = 0; j < 9; j++) {
                float4 f = rp[j];
                r[4 * j + 0] = f.x; r[4 * j + 1] = f.y;
                r[4 * j + 2] = f.z; r[4 * j + 3] = f.w;
            }
#pragma unroll
            for (int kw = 0; kw < 5; kw++) {
                float wv = wt_s[ci][kh * 5 + kw][co];
#pragma unroll
                for (int w = 0; w < 32; w++)
                    acc[w] += wv * r[w + kw];
            }
        }
    }

    // relu + maxpool(2) + sum over this thread's 16 pooled outputs
    float s = 0.f;
#pragma unroll
    for (int i = 0; i < 16; i++)
        s += fmaxf(fmaxf(acc[2 * i], acc[2 * i + 1]), 0.f);

    red[h][co] = s;
    __syncthreads();
    if (h == 0) {
        float tot = 0.f;
#pragma unroll
        for (int hh = 0; hh < 8; hh++) tot += red[hh][co];
        g_part[(b * C2 + co) * 32 + wt] = tot;
    }
}

// ---------------------------------------------------------------------------
// Kernel 3: mean -> glob layernorm -> v -> attn_out (attn==1) -> mlp -> out
// Grid: 64 blocks (one per batch row), 64 threads.
// ---------------------------------------------------------------------------
__global__ __launch_bounds__(64) void head_kernel(
    const float* __restrict__ wg,  const float* __restrict__ bg,
    const float* __restrict__ gg,  const float* __restrict__ beg,
    const float* __restrict__ ipw, const float* __restrict__ ipb,
    const float* __restrict__ ow,  const float* __restrict__ ob,
    const float* __restrict__ m1w, const float* __restrict__ m1b,
    const float* __restrict__ m2w, const float* __restrict__ m2b,
    float* __restrict__ out)
{
    int b = blockIdx.x;
    int t = threadIdx.x;
    __shared__ float gs[32], a[64], buf[64], vv[64], ao[64], hh[32];

    if (t < 32) {
        float s = 0.f;
#pragma unroll
        for (int wt = 0; wt < 32; wt++) s += g_part[(b * C2 + t) * 32 + wt];
        gs[t] = s * (1.0f / 4096.0f);
    }
    __syncthreads();

    // glob pre-activation: relu(g @ w_glob + b_glob)
    float pre = bg[t];
#pragma unroll
    for (int i = 0; i < 32; i++) pre += gs[i] * wg[i * 64 + t];
    pre = fmaxf(pre, 0.f);

    // layernorm over E=64 (two-pass)
    buf[t] = pre;
    __syncthreads();
#pragma unroll
    for (int off = 32; off > 0; off >>= 1) {
        if (t < off) buf[t] += buf[t + off];
        __syncthreads();
    }
    float mean = buf[0] * (1.0f / 64.0f);
    __syncthreads();
    float d = pre - mean;
    buf[t] = d * d;
    __syncthreads();
#pragma unroll
    for (int off = 32; off > 0; off >>= 1) {
        if (t < off) buf[t] += buf[t + off];
        __syncthreads();
    }
    float var = buf[0] * (1.0f / 64.0f);
    float gl = d * rsqrtf(var + 1e-5f) * gg[t] + beg[t];
    a[t] = gl;
    __syncthreads();

    // v = glob @ wv.T + bv  (wv = in_proj_w rows 128..191)
    float v_ = ipb[128 + t];
#pragma unroll
    for (int e = 0; e < 64; e++) v_ += a[e] * ipw[(128 + t) * 64 + e];
    vv[t] = v_;
    __syncthreads();

    // attn == 1 (softmax over singleton axis) -> attn_out = v @ out_w.T + out_b
    float aov = ob[t];
#pragma unroll
    for (int j = 0; j < 64; j++) aov += vv[j] * ow[t * 64 + j];
    ao[t] = aov;
    __syncthreads();

    if (t < 32) {
        float hm = m1b[t];
#pragma unroll
        for (int e = 0; e < 64; e++) hm += ao[e] * m1w[e * 32 + t];
        hh[t] = fmaxf(hm, 0.f);
    }
    __syncthreads();

    if (t < 10) {
        float o = m2b[t];
#pragma unroll
        for (int m = 0; m < 32; m++) o += hh[m] * m2w[m * 10 + t];
        out[b * 10 + t] = o;
    }
}

// ---------------------------------------------------------------------------
// Launch
// ---------------------------------------------------------------------------
extern "C" void kernel_launch(void* const* d_in, const int* in_sizes, int n_in,
                              void* d_out, int out_size)
{
    const float* x    = (const float*)d_in[0];
    // d_in[1..5]: shapelets / w_loc / b_loc / g_loc / be_loc — dead code (attn==1)
    const float* c1w  = (const float*)d_in[6];
    const float* c1b  = (const float*)d_in[7];
    const float* c2w  = (const float*)d_in[8];
    const float* c2b  = (const float*)d_in[9];
    const float* wg   = (const float*)d_in[10];
    const float* bg   = (const float*)d_in[11];
    const float* gg   = (const float*)d_in[12];
    const float* beg  = (const float*)d_in[13];
    const float* ipw  = (const float*)d_in[14];
    const float* ipb  = (const float*)d_in[15];
    const float* ow   = (const float*)d_in[16];
    const float* ob   = (const float*)d_in[17];
    const float* m1w  = (const float*)d_in[18];
    const float* m1b  = (const float*)d_in[19];
    const float* m2w  = (const float*)d_in[20];
    const float* m2b  = (const float*)d_in[21];
    float* out = (float*)d_out;

    dim3 g1(W1P / 256, H_, B_ * C1);   // (4, 8, 1024)
    conv1_pool_kernel<<<g1, 256>>>(x, c1w, c1b);

    dim3 g2(32, B_);                    // 2048 blocks
    conv2_pool_kernel<<<g2, 256>>>(c2w, c2b);

    head_kernel<<<B_, 64>>>(wg, bg, gg, beg, ipw, ipb, ow, ob,
                            m1w, m1b, m2w, m2b, out);
}

// round 3
// speedup vs baseline: 1.0306x; 1.0306x over previous
#include <cuda_runtime.h>
#include <cuda_bf16.h>

// ---------------------------------------------------------------------------
// LocalGlobalCrossAttentionModel — round 3
// softmax over singleton axis == 1.0 -> shapelet/local branch is dead code.
// Pipeline: conv1+pool (smem-shared across co) -> conv2+pool (packed f32x2
// FFMA2) -> mean -> layernorm -> v -> out -> mlp.
// ---------------------------------------------------------------------------

#define B_  64
#define H_  8
#define W1_ 2048
#define W1P 1024
#define C1  16
#define C2  32

__device__ float g_h1[B_ * C1 * H_ * W1P];   // pooled conv1 output
__device__ float g_part[B_ * C2 * 32];       // per-(b,co,wtile) partials

// packed f32x2 FMA: d = a*b + d (two independent fp32 lanes, rn)
#define FMA2(d, a, b) \
    asm("fma.rn.f32x2 %0, %1, %2, %0;" : "+l"(d) : "l"(a), "l"(b))

// ---------------------------------------------------------------------------
// Kernel 1: conv1 (1->16ch, 3x5, pad 1,2) + relu + maxpool(w/2).
// Block = (b, h, tile of 128 pooled cols). x tile loaded to smem ONCE,
// reused by all 16 output channels. 256 thr = (co 0..15) x (wsub 0..15),
// each thread computes 8 pooled outputs.
// ---------------------------------------------------------------------------
__global__ __launch_bounds__(256) void conv1_pool_kernel(
    const float* __restrict__ x,
    const float* __restrict__ w1,
    const float* __restrict__ b1)
{
    int b   = blockIdx.z;
    int h   = blockIdx.y;
    int wp0 = blockIdx.x * 128;          // pooled col base
    int c0  = wp0 * 2;                   // input col base

    __shared__ __align__(16) float xs[3][264];  // cols c0-2 .. c0+257

    for (int idx = threadIdx.x; idx < 3 * 260; idx += 256) {
        int r = idx / 260;
        int j = idx - r * 260;
        int hr = h - 1 + r;
        int c  = c0 - 2 + j;
        float v = 0.f;
        if (hr >= 0 && hr < H_ && c >= 0 && c < W1_)
            v = x[(b * H_ + hr) * W1_ + c];
        xs[r][j] = v;
    }
    __syncthreads();

    int t  = threadIdx.x;
    int co = t >> 4;
    int ws = t & 15;
    int base = ws * 16;                  // local conv col base (16 conv outs)

    float wgt[15];
#pragma unroll
    for (int i = 0; i < 15; i++) wgt[i] = __ldg(&w1[co * 15 + i]);
    float bias = __ldg(&b1[co]);

    float acc[16];
#pragma unroll
    for (int j = 0; j < 16; j++) acc[j] = bias;

#pragma unroll
    for (int kh = 0; kh < 3; kh++) {
        float r_[20];
        const float4* rp = reinterpret_cast<const float4*>(&xs[kh][base]);
#pragma unroll
        for (int q = 0; q < 5; q++) {
            float4 f = rp[q];
            r_[4 * q + 0] = f.x; r_[4 * q + 1] = f.y;
            r_[4 * q + 2] = f.z; r_[4 * q + 3] = f.w;
        }
#pragma unroll
        for (int kw = 0; kw < 5; kw++) {
            float w = wgt[kh * 5 + kw];
#pragma unroll
            for (int j = 0; j < 16; j++)
                acc[j] += w * r_[j + kw];
        }
    }

    // relu + maxpool over width pairs -> 8 pooled outputs, vector store
    float pr[8];
#pragma unroll
    for (int p = 0; p < 8; p++)
        pr[p] = fmaxf(fmaxf(acc[2 * p], acc[2 * p + 1]), 0.f);

    float* dst = &g_h1[((b * C1 + co) * H_ + h) * W1P + wp0 + ws * 8];
    reinterpret_cast<float4*>(dst)[0] = make_float4(pr[0], pr[1], pr[2], pr[3]);
    reinterpret_cast<float4*>(dst)[1] = make_float4(pr[4], pr[5], pr[6], pr[7]);
}

// ---------------------------------------------------------------------------
// Kernel 2: conv2 (16->32ch, 3x5, pad 1,2) + relu + maxpool + partial mean.
// Packed f32x2: accumulator pair = outputs (2i, 2i+1). Aligned data pairs
// free via ulonglong2 smem loads; odd-offset pairs via one mov.b64 each.
// Block 256 = (co 0..31) x (h 0..7); warp = fixed h, lanes = co (weight
// reads conflict-free, data reads broadcast).
// ---------------------------------------------------------------------------
__global__ __launch_bounds__(256, 2) void conv2_pool_kernel(
    const float* __restrict__ w2,
    const float* __restrict__ b2)
{
    int b   = blockIdx.y;
    int wt  = blockIdx.x;
    int tid = threadIdx.x;
    int co  = tid & 31;
    int h   = tid >> 5;

    __shared__ __align__(16) float wt_s[16][15][32];  // [ci][k][co]
    __shared__ __align__(16) float in_s[16][10][40];  // [ci][h pad][col]
    __shared__ float red[8][33];

    for (int idx = tid; idx < 16 * 15 * 32; idx += 256) {
        int c_ = idx & 31;
        int rest = idx >> 5;
        int k  = rest % 15;
        int ci = rest / 15;
        wt_s[ci][k][c_] = w2[(c_ * 16 + ci) * 15 + k];
    }
    int cbase = wt * 32 - 2;
    for (int idx = tid; idx < 16 * 10 * 36; idx += 256) {
        int j = idx % 36;
        int rest = idx / 36;
        int r  = rest % 10;
        int ci = rest / 10;
        int hr = r - 1;
        int c  = cbase + j;
        float v = 0.f;
        if (hr >= 0 && hr < H_ && c >= 0 && c < W1P)
            v = g_h1[((b * C1 + ci) * H_ + hr) * W1P + c];
        in_s[ci][r][j] = v;
    }
    __syncthreads();

    float bias = __ldg(&b2[co]);
    unsigned long long acc2[16];
    {
        unsigned int bi = __float_as_uint(bias);
        unsigned long long bp;
        asm("mov.b64 %0, {%1, %1};" : "=l"(bp) : "r"(bi));
#pragma unroll
        for (int i = 0; i < 16; i++) acc2[i] = bp;
    }

    for (int ci = 0; ci < 16; ci++) {
#pragma unroll
        for (int kh = 0; kh < 3; kh++) {
            // aligned pairs A[j] = (r[2j], r[2j+1]), j = 0..17
            unsigned long long A[18];
            const ulonglong2* rp =
                reinterpret_cast<const ulonglong2*>(&in_s[ci][h + kh][0]);
#pragma unroll
            for (int q = 0; q < 9; q++) {
                ulonglong2 v = rp[q];
                A[2 * q] = v.x; A[2 * q + 1] = v.y;
            }
            // odd pairs Bp[j] = (r[2j+1], r[2j+2]), j = 0..16
            unsigned long long Bp[17];
#pragma unroll
            for (int j = 0; j < 17; j++) {
                unsigned int hi = (unsigned int)(A[j] >> 32);
                unsigned int lo = (unsigned int)(A[j + 1]);
                asm("mov.b64 %0, {%1, %2};" : "=l"(Bp[j]) : "r"(hi), "r"(lo));
            }
#pragma unroll
            for (int kw = 0; kw < 5; kw++) {
                unsigned int wi = __float_as_uint(wt_s[ci][kh * 5 + kw][co]);
                unsigned long long wp;
                asm("mov.b64 %0, {%1, %1};" : "=l"(wp) : "r"(wi));
                if ((kw & 1) == 0) {
                    int off = kw >> 1;
#pragma unroll
                    for (int i = 0; i < 16; i++)
                        FMA2(acc2[i], wp, A[i + off]);
                } else {
                    int off = (kw - 1) >> 1;
#pragma unroll
                    for (int i = 0; i < 16; i++)
                        FMA2(acc2[i], wp, Bp[i + off]);
                }
            }
        }
    }

    // relu + maxpool(2) + sum of this thread's 16 pooled outputs
    float s = 0.f;
#pragma unroll
    for (int i = 0; i < 16; i++) {
        float lo = __uint_as_float((unsigned int)acc2[i]);
        float hi = __uint_as_float((unsigned int)(acc2[i] >> 32));
        s += fmaxf(fmaxf(lo, hi), 0.f);
    }

    red[h][co] = s;
    __syncthreads();
    if (h == 0) {
        float tot = 0.f;
#pragma unroll
        for (int hh = 0; hh < 8; hh++) tot += red[hh][co];
        g_part[(b * C2 + co) * 32 + wt] = tot;
    }
}

// ---------------------------------------------------------------------------
// Kernel 3: mean -> glob layernorm -> v -> attn_out (attn==1) -> mlp -> out
// ---------------------------------------------------------------------------
__global__ __launch_bounds__(64) void head_kernel(
    const float* __restrict__ wg,  const float* __restrict__ bg,
    const float* __restrict__ gg,  const float* __restrict__ beg,
    const float* __restrict__ ipw, const float* __restrict__ ipb,
    const float* __restrict__ ow,  const float* __restrict__ ob,
    const float* __restrict__ m1w, const float* __restrict__ m1b,
    const float* __restrict__ m2w, const float* __restrict__ m2b,
    float* __restrict__ out)
{
    int b = blockIdx.x;
    int t = threadIdx.x;
    __shared__ float gs[32], a[64], buf[64], vv[64], ao[64], hh[32];

    if (t < 32) {
        float s = 0.f;
#pragma unroll
        for (int wt = 0; wt < 32; wt++) s += g_part[(b * C2 + t) * 32 + wt];
        gs[t] = s * (1.0f / 4096.0f);
    }
    __syncthreads();

    float pre = bg[t];
#pragma unroll
    for (int i = 0; i < 32; i++) pre += gs[i] * wg[i * 64 + t];
    pre = fmaxf(pre, 0.f);

    buf[t] = pre;
    __syncthreads();
#pragma unroll
    for (int off = 32; off > 0; off >>= 1) {
        if (t < off) buf[t] += buf[t + off];
        __syncthreads();
    }
    float mean = buf[0] * (1.0f / 64.0f);
    __syncthreads();
    float d = pre - mean;
    buf[t] = d * d;
    __syncthreads();
#pragma unroll
    for (int off = 32; off > 0; off >>= 1) {
        if (t < off) buf[t] += buf[t + off];
        __syncthreads();
    }
    float var = buf[0] * (1.0f / 64.0f);
    float gl = d * rsqrtf(var + 1e-5f) * gg[t] + beg[t];
    a[t] = gl;
    __syncthreads();

    float v_ = ipb[128 + t];
#pragma unroll
    for (int e = 0; e < 64; e++) v_ += a[e] * ipw[(128 + t) * 64 + e];
    vv[t] = v_;
    __syncthreads();

    float aov = ob[t];
#pragma unroll
    for (int j = 0; j < 64; j++) aov += vv[j] * ow[t * 64 + j];
    ao[t] = aov;
    __syncthreads();

    if (t < 32) {
        float hm = m1b[t];
#pragma unroll
        for (int e = 0; e < 64; e++) hm += ao[e] * m1w[e * 32 + t];
        hh[t] = fmaxf(hm, 0.f);
    }
    __syncthreads();

    if (t < 10) {
        float o = m2b[t];
#pragma unroll
        for (int m = 0; m < 32; m++) o += hh[m] * m2w[m * 10 + t];
        out[b * 10 + t] = o;
    }
}

// ---------------------------------------------------------------------------
extern "C" void kernel_launch(void* const* d_in, const int* in_sizes, int n_in,
                              void* d_out, int out_size)
{
    const float* x    = (const float*)d_in[0];
    const float* c1w  = (const float*)d_in[6];
    const float* c1b  = (const float*)d_in[7];
    const float* c2w  = (const float*)d_in[8];
    const float* c2b  = (const float*)d_in[9];
    const float* wg   = (const float*)d_in[10];
    const float* bg   = (const float*)d_in[11];
    const float* gg   = (const float*)d_in[12];
    const float* beg  = (const float*)d_in[13];
    const float* ipw  = (const float*)d_in[14];
    const float* ipb  = (const float*)d_in[15];
    const float* ow   = (const float*)d_in[16];
    const float* ob   = (const float*)d_in[17];
    const float* m1w  = (const float*)d_in[18];
    const float* m1b  = (const float*)d_in[19];
    const float* m2w  = (const float*)d_in[20];
    const float* m2b  = (const float*)d_in[21];
    float* out = (float*)d_out;

    dim3 g1(W1P / 128, H_, B_);          // (8, 8, 64)
    conv1_pool_kernel<<<g1, 256>>>(x, c1w, c1b);

    dim3 g2(32, B_);
    conv2_pool_kernel<<<g2, 256>>>(c2w, c2b);

    head_kernel<<<B_, 64>>>(wg, bg, gg, beg, ipw, ipb, ow, ob,
                            m1w, m1b, m2w, m2b, out);
}

// round 5
// speedup vs baseline: 2.1246x; 2.0614x over previous
#include <cuda_runtime.h>
#include <cuda_bf16.h>
#include <cstdint>

// ---------------------------------------------------------------------------
// LocalGlobalCrossAttentionModel — round 5
// softmax over singleton axis == 1.0 -> shapelet/local branch dead code.
// conv1+pool (fp32, bf16 interleaved out) ->
// conv2+pool as mma.sync.m16n8k16 bf16 GEMM (tcgen05 unavailable: harness
// compiles for compute_103 base target) -> mean -> LN -> v -> out -> mlp.
// ---------------------------------------------------------------------------

#define B_  64
#define H_  8
#define W1_ 2048
#define W1P 1024
#define C1  16
#define C2  32
#define KK  240              // 15 * 16
#define KP  248              // padded K (496B row stride, conflict-free)

// conv1 output, bf16, [b][h][w][ci] (ci contiguous -> 32B granules)
__device__ __nv_bfloat16 g_h1b[B_ * H_ * W1P * C1];
// conv2 weights as B^T row-major [co][k], bf16
__device__ __nv_bfloat16 g_w2b[C2 * KK];
// per-(b,co,tile) pooled partial sums; tile = h*8 + wt
__device__ float g_part[B_ * C2 * 64];

__device__ __forceinline__ uint32_t smem_u32(const void* p) {
    uint32_t a;
    asm("{ .reg .u64 t; cvta.to.shared.u64 t, %1; cvt.u32.u64 %0, t; }"
        : "=r"(a) : "l"(p));
    return a;
}

#define LDMATRIX_X4(r0, r1, r2, r3, addr)                                   \
    asm volatile("ldmatrix.sync.aligned.m8n8.x4.shared.b16 "                \
                 "{%0, %1, %2, %3}, [%4];"                                  \
                 : "=r"(r0), "=r"(r1), "=r"(r2), "=r"(r3) : "r"(addr))

#define MMA_16816(c, a, b)                                                  \
    asm volatile("mma.sync.aligned.m16n8k16.row.col.f32.bf16.bf16.f32 "     \
                 "{%0, %1, %2, %3}, {%4, %5, %6, %7}, {%8, %9}, "           \
                 "{%0, %1, %2, %3};"                                        \
                 : "+f"((c)[0]), "+f"((c)[1]), "+f"((c)[2]), "+f"((c)[3])   \
                 : "r"((a)[0]), "r"((a)[1]), "r"((a)[2]), "r"((a)[3]),      \
                   "r"((b)[0]), "r"((b)[1]))

// ---------------------------------------------------------------------------
// Kernel 0: conv2 weights -> B^T [co][k] bf16, k = (kh*5+kw)*16 + ci
// ---------------------------------------------------------------------------
__global__ void prep_w2_kernel(const float* __restrict__ w2)
{
    for (int idx = threadIdx.x; idx < C2 * 15 * C1; idx += 128) {
        int ci   = idx & 15;
        int khkw = (idx >> 4) % 15;
        int co   = idx / (15 * 16);
        g_w2b[co * KK + khkw * 16 + ci] =
            __float2bfloat16(w2[(co * 16 + ci) * 15 + khkw]);
    }
}

// ---------------------------------------------------------------------------
// Kernel 1: conv1 (1->16ch, 3x5, pad 1,2) + relu + maxpool(w/2).
// Output bf16 interleaved [b][h][w][ci] via smem transpose stage.
// ---------------------------------------------------------------------------
__global__ __launch_bounds__(256) void conv1_pool_kernel(
    const float* __restrict__ x,
    const float* __restrict__ w1,
    const float* __restrict__ b1)
{
    int b   = blockIdx.z;
    int h   = blockIdx.y;
    int wp0 = blockIdx.x * 128;
    int c0  = wp0 * 2;

    __shared__ __align__(16) float xs[3][264];
    __shared__ __align__(16) __nv_bfloat16 stg[128][16];

    for (int idx = threadIdx.x; idx < 3 * 260; idx += 256) {
        int r = idx / 260;
        int j = idx - r * 260;
        int hr = h - 1 + r;
        int c  = c0 - 2 + j;
        float v = 0.f;
        if (hr >= 0 && hr < H_ && c >= 0 && c < W1_)
            v = x[(b * H_ + hr) * W1_ + c];
        xs[r][j] = v;
    }
    __syncthreads();

    int t  = threadIdx.x;
    int co = t >> 4;
    int ws = t & 15;
    int base = ws * 16;

    float wgt[15];
#pragma unroll
    for (int i = 0; i < 15; i++) wgt[i] = __ldg(&w1[co * 15 + i]);
    float bias = __ldg(&b1[co]);

    float acc[16];
#pragma unroll
    for (int j = 0; j < 16; j++) acc[j] = bias;

#pragma unroll
    for (int kh = 0; kh < 3; kh++) {
        float r_[20];
        const float4* rp = reinterpret_cast<const float4*>(&xs[kh][base]);
#pragma unroll
        for (int q = 0; q < 5; q++) {
            float4 f = rp[q];
            r_[4 * q + 0] = f.x; r_[4 * q + 1] = f.y;
            r_[4 * q + 2] = f.z; r_[4 * q + 3] = f.w;
        }
#pragma unroll
        for (int kw = 0; kw < 5; kw++) {
            float w = wgt[kh * 5 + kw];
#pragma unroll
            for (int j = 0; j < 16; j++)
                acc[j] += w * r_[j + kw];
        }
    }

#pragma unroll
    for (int p = 0; p < 8; p++)
        stg[ws * 8 + p][co] =
            __float2bfloat16(fmaxf(fmaxf(acc[2 * p], acc[2 * p + 1]), 0.f));
    __syncthreads();

    uint4 v = reinterpret_cast<const uint4*>(stg)[t];
    reinterpret_cast<uint4*>(
        &g_h1b[((size_t)(b * H_ + h) * W1P + wp0) * C1])[t] = v;
}

// ---------------------------------------------------------------------------
// Kernel 2: conv2 (16->32ch, 3x5) + relu + maxpool + partial mean,
// via mma.sync m16n8k16 bf16. Tile = (b, h, 128-wide w block).
// A[m=128][k=240] im2col in smem (row stride KP=248), B^T[32][240] copied.
// 4 warps x (2 m-tiles x 4 n-tiles x 15 k-steps) mma.
// ---------------------------------------------------------------------------
#define AS_OFF   0
#define AS_BYTES (128 * KP * 2)                 // 63488
#define BS_OFF   AS_BYTES
#define BS_BYTES (C2 * KP * 2)                  // 15872
#define DS_OFF   (BS_OFF + BS_BYTES)            // 79360
#define DS_BYTES (128 * 33 * 4)                 // 16896
#define BIAS_OFF (DS_OFF + DS_BYTES)            // 96256
#define RED_OFF  (BIAS_OFF + 128)               // 96384
#define SMEM_BYTES (RED_OFF + 4 * 33 * 4 + 16)  // ~96928

__global__ __launch_bounds__(128) void conv2_mma_kernel(
    const float* __restrict__ b2)
{
    extern __shared__ __align__(16) char sm[];
    __nv_bfloat16* As = (__nv_bfloat16*)(sm + AS_OFF);
    __nv_bfloat16* Bs = (__nv_bfloat16*)(sm + BS_OFF);
    float* Ds     = (float*)(sm + DS_OFF);      // [128][33]
    float* bias_s = (float*)(sm + BIAS_OFF);
    float* red    = (float*)(sm + RED_OFF);     // [4][33]

    int b  = blockIdx.z;
    int h  = blockIdx.y;
    int wt = blockIdx.x;
    int wbase = wt * 128;
    int tid  = threadIdx.x;
    int wid  = tid >> 5;
    int lane = tid & 31;

    if (tid < 32) bias_s[tid] = b2[tid];

    // ---- im2col A: thread = m row, 15 granules of 32B, coalesced loads ----
    {
        int m = tid;
        char* arow = (char*)&As[m * KP];
#pragma unroll
        for (int khkw = 0; khkw < 15; khkw++) {
            const int kh = khkw / 5;
            const int kw = khkw % 5;
            int row  = h + kh - 1;
            int wsrc = wbase + m + kw - 2;
            uint4 h0 = make_uint4(0, 0, 0, 0), h1 = make_uint4(0, 0, 0, 0);
            if (row >= 0 && row < H_ && wsrc >= 0 && wsrc < W1P) {
                const uint4* p = reinterpret_cast<const uint4*>(
                    &g_h1b[((size_t)(b * H_ + row) * W1P + wsrc) * C1]);
                h0 = p[0]; h1 = p[1];
            }
            reinterpret_cast<uint4*>(arow + khkw * 32)[0] = h0;
            reinterpret_cast<uint4*>(arow + khkw * 32)[1] = h1;
        }
    }
    // ---- copy B^T (32 rows x 240 -> stride 248) ----
    for (int idx = tid; idx < C2 * 30; idx += 128) {
        int r = idx / 30;
        int c16 = idx % 30;
        reinterpret_cast<uint4*>((char*)&Bs[r * KP])[c16] =
            reinterpret_cast<const uint4*>((char*)&g_w2b[r * KK])[c16];
    }
    __syncthreads();

    // ---- MMA main loop ----
    float acc[2][4][4];
#pragma unroll
    for (int mt = 0; mt < 2; mt++)
#pragma unroll
        for (int nt = 0; nt < 4; nt++)
#pragma unroll
            for (int i = 0; i < 4; i++) acc[mt][nt][i] = 0.f;

    uint32_t as_base = smem_u32(As);
    uint32_t bs_base = smem_u32(Bs);
    int half = lane >> 4;          // A: k-half select
    int arow_l = lane & 15;
    int quad = lane >> 3;          // B: mats
    int bw   = lane & 7;

#pragma unroll
    for (int s = 0; s < 15; s++) {
        int k0 = s * 16;
        uint32_t a[2][4];
#pragma unroll
        for (int mt = 0; mt < 2; mt++) {
            int mrow = wid * 32 + mt * 16 + arow_l;
            uint32_t addr = as_base + (uint32_t)(mrow * (KP * 2)
                           + (k0 + half * 8) * 2);
            LDMATRIX_X4(a[mt][0], a[mt][1], a[mt][2], a[mt][3], addr);
        }
        uint32_t bfr[4][2];
#pragma unroll
        for (int ntp = 0; ntp < 2; ntp++) {
            int nrow = ntp * 16 + (quad >> 1) * 8 + bw;
            uint32_t addr = bs_base + (uint32_t)(nrow * (KP * 2)
                           + (k0 + (quad & 1) * 8) * 2);
            uint32_t r0, r1, r2, r3;
            LDMATRIX_X4(r0, r1, r2, r3, addr);
            bfr[2 * ntp][0] = r0;  bfr[2 * ntp][1] = r1;
            bfr[2 * ntp + 1][0] = r2;  bfr[2 * ntp + 1][1] = r3;
        }
#pragma unroll
        for (int mt = 0; mt < 2; mt++)
#pragma unroll
            for (int nt = 0; nt < 4; nt++)
                MMA_16816(acc[mt][nt], a[mt], bfr[nt]);
    }

    // ---- write D fragments to smem [128][33] ----
    int gid = lane >> 2;
    int tg  = lane & 3;
#pragma unroll
    for (int mt = 0; mt < 2; mt++) {
#pragma unroll
        for (int nt = 0; nt < 4; nt++) {
            int m0 = wid * 32 + mt * 16 + gid;
            int n0 = nt * 8 + tg * 2;
            Ds[m0 * 33 + n0]           = acc[mt][nt][0];
            Ds[m0 * 33 + n0 + 1]       = acc[mt][nt][1];
            Ds[(m0 + 8) * 33 + n0]     = acc[mt][nt][2];
            Ds[(m0 + 8) * 33 + n0 + 1] = acc[mt][nt][3];
        }
    }
    __syncthreads();

    // ---- bias + relu + maxpool(2 along m) + partial sum ----
    {
        int co  = tid & 31;
        int seg = tid >> 5;          // 4 segments of 16 pooled outputs
        float bs = bias_s[co];
        float s = 0.f;
#pragma unroll
        for (int i = 0; i < 16; i++) {
            int m = seg * 32 + 2 * i;
            float v0 = Ds[m * 33 + co] + bs;
            float v1 = Ds[(m + 1) * 33 + co] + bs;
            s += fmaxf(fmaxf(v0, v1), 0.f);
        }
        red[seg * 33 + co] = s;
    }
    __syncthreads();
    if (tid < 32) {
        float tot = red[tid] + red[33 + tid] + red[66 + tid] + red[99 + tid];
        g_part[(b * C2 + tid) * 64 + h * 8 + wt] = tot;
    }
}

// ---------------------------------------------------------------------------
// Kernel 3: mean -> glob layernorm -> v -> attn_out (attn==1) -> mlp -> out
// ---------------------------------------------------------------------------
__global__ __launch_bounds__(64) void head_kernel(
    const float* __restrict__ wg,  const float* __restrict__ bg,
    const float* __restrict__ gg,  const float* __restrict__ beg,
    const float* __restrict__ ipw, const float* __restrict__ ipb,
    const float* __restrict__ ow,  const float* __restrict__ ob,
    const float* __restrict__ m1w, const float* __restrict__ m1b,
    const float* __restrict__ m2w, const float* __restrict__ m2b,
    float* __restrict__ out)
{
    int b = blockIdx.x;
    int t = threadIdx.x;
    __shared__ float gs[32], a[64], buf[64], vv[64], ao[64], hh[32];

    if (t < 32) {
        float s = 0.f;
#pragma unroll
        for (int i = 0; i < 64; i++) s += g_part[(b * C2 + t) * 64 + i];
        gs[t] = s * (1.0f / 4096.0f);
    }
    __syncthreads();

    float pre = bg[t];
#pragma unroll
    for (int i = 0; i < 32; i++) pre += gs[i] * wg[i * 64 + t];
    pre = fmaxf(pre, 0.f);

    buf[t] = pre;
    __syncthreads();
#pragma unroll
    for (int off = 32; off > 0; off >>= 1) {
        if (t < off) buf[t] += buf[t + off];
        __syncthreads();
    }
    float mean = buf[0] * (1.0f / 64.0f);
    __syncthreads();
    float d = pre - mean;
    buf[t] = d * d;
    __syncthreads();
#pragma unroll
    for (int off = 32; off > 0; off >>= 1) {
        if (t < off) buf[t] += buf[t + off];
        __syncthreads();
    }
    float var = buf[0] * (1.0f / 64.0f);
    float gl = d * rsqrtf(var + 1e-5f) * gg[t] + beg[t];
    a[t] = gl;
    __syncthreads();

    float v_ = ipb[128 + t];
#pragma unroll
    for (int e = 0; e < 64; e++) v_ += a[e] * ipw[(128 + t) * 64 + e];
    vv[t] = v_;
    __syncthreads();

    float aov = ob[t];
#pragma unroll
    for (int j = 0; j < 64; j++) aov += vv[j] * ow[t * 64 + j];
    ao[t] = aov;
    __syncthreads();

    if (t < 32) {
        float hm = m1b[t];
#pragma unroll
        for (int e = 0; e < 64; e++) hm += ao[e] * m1w[e * 32 + t];
        hh[t] = fmaxf(hm, 0.f);
    }
    __syncthreads();

    if (t < 10) {
        float o = m2b[t];
#pragma unroll
        for (int m = 0; m < 32; m++) o += hh[m] * m2w[m * 10 + t];
        out[b * 10 + t] = o;
    }
}

// ---------------------------------------------------------------------------
extern "C" void kernel_launch(void* const* d_in, const int* in_sizes, int n_in,
                              void* d_out, int out_size)
{
    const float* x    = (const float*)d_in[0];
    const float* c1w  = (const float*)d_in[6];
    const float* c1b  = (const float*)d_in[7];
    const float* c2w  = (const float*)d_in[8];
    const float* c2b  = (const float*)d_in[9];
    const float* wg   = (const float*)d_in[10];
    const float* bg   = (const float*)d_in[11];
    const float* gg   = (const float*)d_in[12];
    const float* beg  = (const float*)d_in[13];
    const float* ipw  = (const float*)d_in[14];
    const float* ipb  = (const float*)d_in[15];
    const float* ow   = (const float*)d_in[16];
    const float* ob   = (const float*)d_in[17];
    const float* m1w  = (const float*)d_in[18];
    const float* m1b  = (const float*)d_in[19];
    const float* m2w  = (const float*)d_in[20];
    const float* m2b  = (const float*)d_in[21];
    float* out = (float*)d_out;

    static int smem_set = 0;
    if (!smem_set) {
        cudaFuncSetAttribute(conv2_mma_kernel,
                             cudaFuncAttributeMaxDynamicSharedMemorySize,
                             SMEM_BYTES);
        smem_set = 1;
    }

    prep_w2_kernel<<<1, 128>>>(c2w);

    dim3 g1(W1P / 128, H_, B_);
    conv1_pool_kernel<<<g1, 256>>>(x, c1w, c1b);

    dim3 g2(8, H_, B_);
    conv2_mma_kernel<<<g2, 128, SMEM_BYTES>>>(c2b);

    head_kernel<<<B_, 64>>>(wg, bg, gg, beg, ipw, ipb, ow, ob,
                            m1w, m1b, m2w, m2b, out);
}

// round 8
// speedup vs baseline: 2.9160x; 1.3725x over previous
#include <cuda_runtime.h>
#include <cuda_bf16.h>
#include <cstdint>

// ---------------------------------------------------------------------------
// LocalGlobalCrossAttentionModel — round 6
// softmax over singleton axis == 1.0 -> shapelet/local branch dead code.
// conv1+pool (fp32, bf16 interleaved out) ->
// conv2+pool as mma.sync bf16 GEMM with shifted-view A (no im2col copy),
// register/shfl epilogue -> mean -> LN -> v -> out -> mlp (wide head).
// ---------------------------------------------------------------------------

#define B_  64
#define H_  8
#define W1_ 2048
#define W1P 1024
#define C1  16
#define C2  32
#define KK  240              // 15 * 16
#define KP  248              // padded K for B (496B stride, conflict-free)

// conv1 output, bf16, [b][h][w][ci] (ci contiguous -> 32B granules)
__device__ __nv_bfloat16 g_h1b[B_ * H_ * W1P * C1];
// conv2 weights as B^T row-major [co][k], bf16
__device__ __nv_bfloat16 g_w2b[C2 * KK];
// per-(b,co,tile) pooled partial sums; tile = h*8 + wt
__device__ float g_part[B_ * C2 * 64];

__device__ __forceinline__ uint32_t smem_u32(const void* p) {
    uint32_t a;
    asm("{ .reg .u64 t; cvta.to.shared.u64 t, %1; cvt.u32.u64 %0, t; }"
        : "=r"(a) : "l"(p));
    return a;
}

#define LDMATRIX_X4(r0, r1, r2, r3, addr)                                   \
    asm volatile("ldmatrix.sync.aligned.m8n8.x4.shared.b16 "                \
                 "{%0, %1, %2, %3}, [%4];"                                  \
                 : "=r"(r0), "=r"(r1), "=r"(r2), "=r"(r3) : "r"(addr))

#define MMA_16816(c, a, b)                                                  \
    asm volatile("mma.sync.aligned.m16n8k16.row.col.f32.bf16.bf16.f32 "     \
                 "{%0, %1, %2, %3}, {%4, %5, %6, %7}, {%8, %9}, "           \
                 "{%0, %1, %2, %3};"                                        \
                 : "+f"((c)[0]), "+f"((c)[1]), "+f"((c)[2]), "+f"((c)[3])   \
                 : "r"((a)[0]), "r"((a)[1]), "r"((a)[2]), "r"((a)[3]),      \
                   "r"((b)[0]), "r"((b)[1]))

// ---------------------------------------------------------------------------
// Kernel 0: conv2 weights -> B^T [co][k] bf16, k = (kh*5+kw)*16 + ci
// ---------------------------------------------------------------------------
__global__ void prep_w2_kernel(const float* __restrict__ w2)
{
    for (int idx = threadIdx.x; idx < C2 * 15 * C1; idx += 128) {
        int ci   = idx & 15;
        int khkw = (idx >> 4) % 15;
        int co   = idx / (15 * 16);
        g_w2b[co * KK + khkw * 16 + ci] =
            __float2bfloat16(w2[(co * 16 + ci) * 15 + khkw]);
    }
}

// ---------------------------------------------------------------------------
// Kernel 1: conv1 (1->16ch, 3x5, pad 1,2) + relu + maxpool(w/2).
// Output bf16 interleaved [b][h][w][ci] via smem transpose stage.
// ---------------------------------------------------------------------------
__global__ __launch_bounds__(256) void conv1_pool_kernel(
    const float* __restrict__ x,
    const float* __restrict__ w1,
    const float* __restrict__ b1)
{
    int b   = blockIdx.z;
    int h   = blockIdx.y;
    int wp0 = blockIdx.x * 128;
    int c0  = wp0 * 2;

    __shared__ __align__(16) float xs[3][264];
    __shared__ __align__(16) __nv_bfloat16 stg[128][16];

    for (int idx = threadIdx.x; idx < 3 * 260; idx += 256) {
        int r = idx / 260;
        int j = idx - r * 260;
        int hr = h - 1 + r;
        int c  = c0 - 2 + j;
        float v = 0.f;
        if (hr >= 0 && hr < H_ && c >= 0 && c < W1_)
            v = x[(b * H_ + hr) * W1_ + c];
        xs[r][j] = v;
    }
    __syncthreads();

    int t  = threadIdx.x;
    int co = t >> 4;
    int ws = t & 15;
    int base = ws * 16;

    float wgt[15];
#pragma unroll
    for (int i = 0; i < 15; i++) wgt[i] = __ldg(&w1[co * 15 + i]);
    float bias = __ldg(&b1[co]);

    float acc[16];
#pragma unroll
    for (int j = 0; j < 16; j++) acc[j] = bias;

#pragma unroll
    for (int kh = 0; kh < 3; kh++) {
        float r_[20];
        const float4* rp = reinterpret_cast<const float4*>(&xs[kh][base]);
#pragma unroll
        for (int q = 0; q < 5; q++) {
            float4 f = rp[q];
            r_[4 * q + 0] = f.x; r_[4 * q + 1] = f.y;
            r_[4 * q + 2] = f.z; r_[4 * q + 3] = f.w;
        }
#pragma unroll
        for (int kw = 0; kw < 5; kw++) {
            float w = wgt[kh * 5 + kw];
#pragma unroll
            for (int j = 0; j < 16; j++)
                acc[j] += w * r_[j + kw];
        }
    }

#pragma unroll
    for (int p = 0; p < 8; p++)
        stg[ws * 8 + p][co] =
            __float2bfloat16(fmaxf(fmaxf(acc[2 * p], acc[2 * p + 1]), 0.f));
    __syncthreads();

    uint4 v = reinterpret_cast<const uint4*>(stg)[t];
    reinterpret_cast<uint4*>(
        &g_h1b[((size_t)(b * H_ + h) * W1P + wp0) * C1])[t] = v;
}

// ---------------------------------------------------------------------------
// Kernel 2: conv2 via mma.sync, shifted-view A.
// A: 3 h-planes of [132 w-rows][16 ci] bf16 at 48B row stride (conflict-free
// ldmatrix). Step (kh,kw) reads plane kh at row offset m+kw — no im2col dup.
// Epilogue fully in registers: bias + relu + maxpool via shfl_xor(4) pairs,
// partial-mean via shfl_xor(8,16) + tiny smem cross-warp reduce.
// ---------------------------------------------------------------------------
#define A_ROWS   136
#define A_RSTR   48
#define A_PLANE  (A_ROWS * A_RSTR)          // 6528

__global__ __launch_bounds__(128) void conv2_mma_kernel(
    const float* __restrict__ b2)
{
    __shared__ __align__(16) char sa[3 * A_PLANE];          // 19584
    __shared__ __align__(16) __nv_bfloat16 Bs[C2 * KP];     // 15872
    __shared__ float bias_s[32];
    __shared__ float red[4 * 32];

    int b  = blockIdx.z;
    int h  = blockIdx.y;
    int wt = blockIdx.x;
    int wbase = wt * 128;
    int tid  = threadIdx.x;
    int wid  = tid >> 5;
    int lane = tid & 31;

    if (tid < 32) bias_s[tid] = b2[tid];

    // ---- fill A planes: rows r=0..131 -> w = wbase-2+r, zero OOB ----
    for (int idx = tid; idx < 3 * 132; idx += 128) {
        int plane = idx / 132;
        int r = idx - plane * 132;
        int row = h + plane - 1;
        int w = wbase - 2 + r;
        uint4 h0 = make_uint4(0, 0, 0, 0), h1 = make_uint4(0, 0, 0, 0);
        if (row >= 0 && row < H_ && w >= 0 && w < W1P) {
            const uint4* p = reinterpret_cast<const uint4*>(
                &g_h1b[((size_t)(b * H_ + row) * W1P + w) * C1]);
            h0 = p[0]; h1 = p[1];
        }
        char* dst = sa + plane * A_PLANE + r * A_RSTR;
        reinterpret_cast<uint4*>(dst)[0] = h0;
        reinterpret_cast<uint4*>(dst)[1] = h1;
    }
    // ---- copy B^T (32 rows x 240 -> stride 248) ----
    for (int idx = tid; idx < C2 * 30; idx += 128) {
        int r = idx / 30;
        int c16 = idx % 30;
        reinterpret_cast<uint4*>((char*)&Bs[r * KP])[c16] =
            reinterpret_cast<const uint4*>((char*)&g_w2b[r * KK])[c16];
    }
    __syncthreads();

    // ---- MMA main loop ----
    float acc[2][4][4];
#pragma unroll
    for (int mt = 0; mt < 2; mt++)
#pragma unroll
        for (int nt = 0; nt < 4; nt++)
#pragma unroll
            for (int i = 0; i < 4; i++) acc[mt][nt][i] = 0.f;

    uint32_t as_base = smem_u32(sa);
    uint32_t bs_base = smem_u32(Bs);
    int half = lane >> 4;
    int arow_l = lane & 15;
    int quad = lane >> 3;
    int bw   = lane & 7;

#pragma unroll
    for (int s = 0; s < 15; s++) {
        const int kh = s / 5;
        const int kw = s % 5;
        int k0 = s * 16;
        uint32_t a[2][4];
#pragma unroll
        for (int mt = 0; mt < 2; mt++) {
            int mrow = wid * 32 + mt * 16 + arow_l;
            uint32_t addr = as_base + (uint32_t)(kh * A_PLANE
                           + (mrow + kw) * A_RSTR + half * 16);
            LDMATRIX_X4(a[mt][0], a[mt][1], a[mt][2], a[mt][3], addr);
        }
        uint32_t bfr[4][2];
#pragma unroll
        for (int ntp = 0; ntp < 2; ntp++) {
            int nrow = ntp * 16 + (quad >> 1) * 8 + bw;
            uint32_t addr = bs_base + (uint32_t)(nrow * (KP * 2)
                           + (k0 + (quad & 1) * 8) * 2);
            uint32_t r0, r1, r2, r3;
            LDMATRIX_X4(r0, r1, r2, r3, addr);
            bfr[2 * ntp][0] = r0;  bfr[2 * ntp][1] = r1;
            bfr[2 * ntp + 1][0] = r2;  bfr[2 * ntp + 1][1] = r3;
        }
#pragma unroll
        for (int mt = 0; mt < 2; mt++)
#pragma unroll
            for (int nt = 0; nt < 4; nt++)
                MMA_16816(acc[mt][nt], a[mt], bfr[nt]);
    }

    // ---- epilogue: bias + relu + maxpool (shfl pair) + partial mean ----
    // fragment: c0,c1 -> row gid, cols n0,n0+1 ; c2,c3 -> row gid+8.
    // maxpool pairs m rows (gid, gid^1) -> shfl_xor lane 4.
    int tg = lane & 3;
    float bc[8];
#pragma unroll
    for (int nt = 0; nt < 4; nt++) {
        bc[2 * nt]     = bias_s[nt * 8 + tg * 2];
        bc[2 * nt + 1] = bias_s[nt * 8 + tg * 2 + 1];
    }
    float part[8];
#pragma unroll
    for (int j = 0; j < 8; j++) part[j] = 0.f;
#pragma unroll
    for (int mt = 0; mt < 2; mt++) {
#pragma unroll
        for (int nt = 0; nt < 4; nt++) {
            float v0 = acc[mt][nt][0] + bc[2 * nt];
            float v1 = acc[mt][nt][1] + bc[2 * nt + 1];
            float v2 = acc[mt][nt][2] + bc[2 * nt];
            float v3 = acc[mt][nt][3] + bc[2 * nt + 1];
            float p0 = __shfl_xor_sync(0xffffffffu, v0, 4);
            float p1 = __shfl_xor_sync(0xffffffffu, v1, 4);
            float p2 = __shfl_xor_sync(0xffffffffu, v2, 4);
            float p3 = __shfl_xor_sync(0xffffffffu, v3, 4);
            part[2 * nt]     += fmaxf(fmaxf(v0, p0), 0.f)
                              + fmaxf(fmaxf(v2, p2), 0.f);
            part[2 * nt + 1] += fmaxf(fmaxf(v1, p1), 0.f)
                              + fmaxf(fmaxf(v3, p3), 0.f);
        }
    }
    // reduce over gid bits 1,2 (lane bits 3,4); lanes 0-3 then hold the
    // full (single-counted) sum over this warp's 16 pooled rows.
#pragma unroll
    for (int j = 0; j < 8; j++) {
        part[j] += __shfl_xor_sync(0xffffffffu, part[j], 8);
        part[j] += __shfl_xor_sync(0xffffffffu, part[j], 16);
    }
    if (lane < 4) {
#pragma unroll
        for (int nt = 0; nt < 4; nt++) {
            red[wid * 32 + nt * 8 + lane * 2]     = part[2 * nt];
            red[wid * 32 + nt * 8 + lane * 2 + 1] = part[2 * nt + 1];
        }
    }
    __syncthreads();
    if (tid < 32) {
        float tot = red[tid] + red[32 + tid] + red[64 + tid] + red[96 + tid];
        g_part[(b * C2 + tid) * 64 + h * 8 + wt] = tot;
    }
}

// ---------------------------------------------------------------------------
// Kernel 3: head — 256 threads, 4-way k-split GEMV stages.
// mean -> relu(g@Wg+b) -> LN -> v -> attn_out (attn==1) -> mlp -> out
// ---------------------------------------------------------------------------
__global__ __launch_bounds__(256) void head_kernel(
    const float* __restrict__ wg,  const float* __restrict__ bg,
    const float* __restrict__ gg,  const float* __restrict__ beg,
    const float* __restrict__ ipw, const float* __restrict__ ipb,
    const float* __restrict__ ow,  const float* __restrict__ ob,
    const float* __restrict__ m1w, const float* __restrict__ m1b,
    const float* __restrict__ m2w, const float* __restrict__ m2b,
    float* __restrict__ out)
{
    int b   = blockIdx.x;
    int tid = threadIdx.x;
    int t   = tid & 63;
    int q   = tid >> 6;
    int lane = tid & 31;
    int wid  = tid >> 5;

    __shared__ float gs[32], a[64], vv[64], ao[64], hh[32];
    __shared__ float pp[4][64];          // aliased as [8][32] where needed
    __shared__ float red2[4];

    // ---- g = mean over 64 partials, 8-way split per co ----
    {
        int co = tid & 31, grp = wid;    // 8 groups of 8
        float s = 0.f;
#pragma unroll
        for (int i = 0; i < 8; i++)
            s += g_part[(b * C2 + co) * 64 + grp * 8 + i];
        ((float*)pp)[grp * 32 + co] = s;
    }
    __syncthreads();
    if (tid < 32) {
        float s = 0.f;
#pragma unroll
        for (int g2 = 0; g2 < 8; g2++) s += ((float*)pp)[g2 * 32 + tid];
        gs[tid] = s * (1.0f / 4096.0f);
    }
    __syncthreads();

    // ---- pre = relu(gs @ wg + bg), k-split 4x8 ----
    {
        float s = 0.f;
#pragma unroll
        for (int i = 0; i < 8; i++) {
            int e = q * 8 + i;
            s += gs[e] * wg[e * 64 + t];
        }
        pp[q][t] = s;
    }
    __syncthreads();
    float pre = 0.f;
    if (tid < 64) {
        pre = pp[0][t] + pp[1][t] + pp[2][t] + pp[3][t] + bg[t];
        pre = fmaxf(pre, 0.f);
    }
    // ---- layernorm over 64 (threads 0..63, shfl reductions) ----
    if (tid < 64) {
        float s = pre;
#pragma unroll
        for (int o = 16; o > 0; o >>= 1) s += __shfl_xor_sync(0xffffffffu, s, o);
        if (lane == 0) red2[wid] = s;
    }
    __syncthreads();
    float mean = (red2[0] + red2[1]) * (1.0f / 64.0f);
    if (tid < 64) {
        float d = pre - mean;
        float s = d * d;
#pragma unroll
        for (int o = 16; o > 0; o >>= 1) s += __shfl_xor_sync(0xffffffffu, s, o);
        if (lane == 0) red2[2 + wid] = s;
    }
    __syncthreads();
    if (tid < 64) {
        float var = (red2[2] + red2[3]) * (1.0f / 64.0f);
        a[t] = (pre - mean) * rsqrtf(var + 1e-5f) * gg[t] + beg[t];
    }
    __syncthreads();

    // ---- v = a @ Wv^T + bv (rows 128..191 of in_proj), k-split 4x16 ----
    {
        float s = 0.f;
#pragma unroll
        for (int i = 0; i < 16; i++) {
            int e = q * 16 + i;
            s += a[e] * ipw[(128 + t) * 64 + e];
        }
        pp[q][t] = s;
    }
    __syncthreads();
    if (tid < 64)
        vv[t] = pp[0][t] + pp[1][t] + pp[2][t] + pp[3][t] + ipb[128 + t];
    __syncthreads();

    // ---- attn_out = vv @ out_w^T + ob ----
    {
        float s = 0.f;
#pragma unroll
        for (int i = 0; i < 16; i++) {
            int j = q * 16 + i;
            s += vv[j] * ow[t * 64 + j];
        }
        pp[q][t] = s;
    }
    __syncthreads();
    if (tid < 64)
        ao[t] = pp[0][t] + pp[1][t] + pp[2][t] + pp[3][t] + ob[t];
    __syncthreads();

    // ---- h = relu(ao @ m1w + b1), 8-way split per output ----
    {
        int t32 = tid & 31, q2 = wid;
        float s = 0.f;
#pragma unroll
        for (int i = 0; i < 8; i++) {
            int e = q2 * 8 + i;
            s += ao[e] * m1w[e * 32 + t32];
        }
        ((float*)pp)[q2 * 32 + t32] = s;
    }
    __syncthreads();
    if (tid < 32) {
        float s = m1b[tid];
#pragma unroll
        for (int g2 = 0; g2 < 8; g2++) s += ((float*)pp)[g2 * 32 + tid];
        hh[tid] = fmaxf(s, 0.f);
    }
    __syncthreads();

    if (tid < 10) {
        float o = m2b[tid];
#pragma unroll
        for (int m = 0; m < 32; m++) o += hh[m] * m2w[m * 10 + tid];
        out[b * 10 + tid] = o;
    }
}

// ---------------------------------------------------------------------------
extern "C" void kernel_launch(void* const* d_in, const int* in_sizes, int n_in,
                              void* d_out, int out_size)
{
    const float* x    = (const float*)d_in[0];
    const float* c1w  = (const float*)d_in[6];
    const float* c1b  = (const float*)d_in[7];
    const float* c2w  = (const float*)d_in[8];
    const float* c2b  = (const float*)d_in[9];
    const float* wg   = (const float*)d_in[10];
    const float* bg   = (const float*)d_in[11];
    const float* gg   = (const float*)d_in[12];
    const float* beg  = (const float*)d_in[13];
    const float* ipw  = (const float*)d_in[14];
    const float* ipb  = (const float*)d_in[15];
    const float* ow   = (const float*)d_in[16];
    const float* ob   = (const float*)d_in[17];
    const float* m1w  = (const float*)d_in[18];
    const float* m1b  = (const float*)d_in[19];
    const float* m2w  = (const float*)d_in[20];
    const float* m2b  = (const float*)d_in[21];
    float* out = (float*)d_out;

    prep_w2_kernel<<<1, 128>>>(c2w);

    dim3 g1(W1P / 128, H_, B_);
    conv1_pool_kernel<<<g1, 256>>>(x, c1w, c1b);

    dim3 g2(8, H_, B_);
    conv2_mma_kernel<<<g2, 128>>>(c2b);

    head_kernel<<<B_, 256>>>(wg, bg, gg, beg, ipw, ipb, ow, ob,
                             m1w, m1b, m2w, m2b, out);
}

// round 10
// speedup vs baseline: 2.9441x; 1.0096x over previous
#include <cuda_runtime.h>
#include <cuda_bf16.h>
#include <cstdint>

// ---------------------------------------------------------------------------
// LocalGlobalCrossAttentionModel — round 9
// softmax over singleton axis == 1.0 -> shapelet/local branch dead code.
// conv1+pool (fp32, h-loop per block, bf16 interleaved out, fused w2 prep) ->
// conv2+pool (mma.sync bf16, shifted-view A, all 8 h per block, register
// epilogue accumulated across h) -> head (all weights prefetched to smem).
// ---------------------------------------------------------------------------

#define B_  64
#define H_  8
#define W1_ 2048
#define W1P 1024
#define C1  16
#define C2  32
#define KK  240              // 15 * 16
#define KP  248              // padded K for B (496B stride, conflict-free)

// conv1 output, bf16, [b][h][w][ci] (ci contiguous -> 32B granules)
__device__ __nv_bfloat16 g_h1b[B_ * H_ * W1P * C1];
// conv2 weights as B^T row-major [co][k], bf16
__device__ __nv_bfloat16 g_w2b[C2 * KK];
// per-(b,co,wt) pooled partial sums (summed over h inside conv2)
__device__ float g_part[B_ * C2 * 8];

__device__ __forceinline__ uint32_t smem_u32(const void* p) {
    uint32_t a;
    asm("{ .reg .u64 t; cvta.to.shared.u64 t, %1; cvt.u32.u64 %0, t; }"
        : "=r"(a) : "l"(p));
    return a;
}

#define LDMATRIX_X4(r0, r1, r2, r3, addr)                                   \
    asm volatile("ldmatrix.sync.aligned.m8n8.x4.shared.b16 "                \
                 "{%0, %1, %2, %3}, [%4];"                                  \
                 : "=r"(r0), "=r"(r1), "=r"(r2), "=r"(r3) : "r"(addr))

#define MMA_16816(c, a, b)                                                  \
    asm volatile("mma.sync.aligned.m16n8k16.row.col.f32.bf16.bf16.f32 "     \
                 "{%0, %1, %2, %3}, {%4, %5, %6, %7}, {%8, %9}, "           \
                 "{%0, %1, %2, %3};"                                        \
                 : "+f"((c)[0]), "+f"((c)[1]), "+f"((c)[2]), "+f"((c)[3])   \
                 : "r"((a)[0]), "r"((a)[1]), "r"((a)[2]), "r"((a)[3]),      \
                   "r"((b)[0]), "r"((b)[1]))

// ---------------------------------------------------------------------------
// Kernel 1: conv1 (1->16ch, 3x5, pad 1,2) + relu + maxpool(w/2), all 8 h per
// block; grid.y==64 branch converts conv2 weights (fused prep).
// ---------------------------------------------------------------------------
__global__ __launch_bounds__(256) void conv1_pool_kernel(
    const float* __restrict__ x,
    const float* __restrict__ w1,
    const float* __restrict__ b1,
    const float* __restrict__ w2)
{
    int tid = threadIdx.x;

    if (blockIdx.y == 64) {               // fused weight-prep branch
        if (blockIdx.x != 0) return;
        for (int idx = tid; idx < C2 * 15 * C1; idx += 256) {
            int ci   = idx & 15;
            int khkw = (idx >> 4) % 15;
            int co   = idx / (15 * 16);
            g_w2b[co * KK + khkw * 16 + ci] =
                __float2bfloat16(w2[(co * 16 + ci) * 15 + khkw]);
        }
        return;
    }

    int b   = blockIdx.y;
    int wp0 = blockIdx.x * 128;
    int c0  = wp0 * 2;

    __shared__ __align__(16) float xs[10][264];           // rows -1..8
    __shared__ __align__(16) __nv_bfloat16 stg[2][128][16];

    // fill all 10 input rows once
#pragma unroll
    for (int p = 0; p < 10; p++) {
        int hr = p - 1;
        for (int j = tid; j < 260; j += 256) {
            int c = c0 - 2 + j;
            float v = 0.f;
            if (hr >= 0 && hr < H_ && c >= 0 && c < W1_)
                v = x[(b * H_ + hr) * W1_ + c];
            xs[p][j] = v;
        }
    }

    int co = tid >> 4;
    int ws = tid & 15;
    int base = ws * 16;

    float wgt[15];
#pragma unroll
    for (int i = 0; i < 15; i++) wgt[i] = __ldg(&w1[co * 15 + i]);
    float bias = __ldg(&b1[co]);

    __syncthreads();

    for (int h = 0; h < 8; h++) {
        float acc[16];
#pragma unroll
        for (int j = 0; j < 16; j++) acc[j] = bias;
#pragma unroll
        for (int kh = 0; kh < 3; kh++) {
            float r_[20];
            const float4* rp = reinterpret_cast<const float4*>(&xs[h + kh][base]);
#pragma unroll
            for (int q = 0; q < 5; q++) {
                float4 f = rp[q];
                r_[4 * q + 0] = f.x; r_[4 * q + 1] = f.y;
                r_[4 * q + 2] = f.z; r_[4 * q + 3] = f.w;
            }
#pragma unroll
            for (int kw = 0; kw < 5; kw++) {
                float w = wgt[kh * 5 + kw];
#pragma unroll
                for (int j = 0; j < 16; j++)
                    acc[j] += w * r_[j + kw];
            }
        }
#pragma unroll
        for (int p = 0; p < 8; p++)
            stg[h & 1][ws * 8 + p][co] =
                __float2bfloat16(fmaxf(fmaxf(acc[2 * p], acc[2 * p + 1]), 0.f));
        __syncthreads();
        uint4 v = reinterpret_cast<const uint4*>(stg[h & 1])[tid];
        reinterpret_cast<uint4*>(
            &g_h1b[((size_t)(b * H_ + h) * W1P + wp0) * C1])[tid] = v;
        // no trailing sync: next write targets the other buffer; the sync in
        // the following iteration orders reuse of this one.
    }
}

// ---------------------------------------------------------------------------
// Kernel 2: conv2 via mma.sync, shifted-view A, ALL 8 h rows per block.
// A: 10 h-planes of [132 w-rows][16 ci] bf16 at 48B row stride, loaded once.
// Step (kh,kw) of tile h reads plane h+kh at row m+kw. Pooled partial sums
// accumulate in registers across the whole h loop; single final reduction.
// ---------------------------------------------------------------------------
#define A_ROWS   136
#define A_RSTR   48
#define A_PLANE  (A_ROWS * A_RSTR)                  // 6528
#define SA_BYTES (10 * A_PLANE)                     // 65280
#define BS_OFF   SA_BYTES
#define BS_BYTES (C2 * KP * 2)                      // 15872
#define BIAS_OFF (BS_OFF + BS_BYTES)                // 81152
#define RED_OFF  (BIAS_OFF + 128)                   // 81280
#define C2_SMEM  (RED_OFF + 512)                    // 81792 -> req 81920

__global__ __launch_bounds__(128) void conv2_mma_kernel(
    const float* __restrict__ b2)
{
    extern __shared__ __align__(16) char sm2[];
    __nv_bfloat16* Bs = (__nv_bfloat16*)(sm2 + BS_OFF);
    float* bias_s = (float*)(sm2 + BIAS_OFF);
    float* red    = (float*)(sm2 + RED_OFF);

    int b  = blockIdx.y;
    int wt = blockIdx.x;
    int wbase = wt * 128;
    int tid  = threadIdx.x;
    int wid  = tid >> 5;
    int lane = tid & 31;

    if (tid < 32) bias_s[tid] = b2[tid];

    // ---- fill 10 A planes (input rows -1..8), rows r -> w = wbase-2+r ----
#pragma unroll
    for (int p = 0; p < 10; p++) {
        int row = p - 1;
        for (int r = tid; r < 132; r += 128) {
            int w = wbase - 2 + r;
            uint4 h0 = make_uint4(0, 0, 0, 0), h1 = make_uint4(0, 0, 0, 0);
            if (row >= 0 && row < H_ && w >= 0 && w < W1P) {
                const uint4* pg = reinterpret_cast<const uint4*>(
                    &g_h1b[((size_t)(b * H_ + row) * W1P + w) * C1]);
                h0 = pg[0]; h1 = pg[1];
            }
            char* dst = sm2 + p * A_PLANE + r * A_RSTR;
            reinterpret_cast<uint4*>(dst)[0] = h0;
            reinterpret_cast<uint4*>(dst)[1] = h1;
        }
    }
    // ---- copy B^T (32 rows x 240 -> stride 248), once per block ----
    for (int idx = tid; idx < C2 * 30; idx += 128) {
        int r = idx / 30;
        int c16 = idx % 30;
        reinterpret_cast<uint4*>((char*)&Bs[r * KP])[c16] =
            reinterpret_cast<const uint4*>((char*)&g_w2b[r * KK])[c16];
    }
    __syncthreads();

    uint32_t as_base = smem_u32(sm2);
    uint32_t bs_base = smem_u32(Bs);
    int half = lane >> 4;
    int arow_l = lane & 15;
    int quad = lane >> 3;
    int bw   = lane & 7;
    int tg   = lane & 3;

    float bc[8];
#pragma unroll
    for (int nt = 0; nt < 4; nt++) {
        bc[2 * nt]     = bias_s[nt * 8 + tg * 2];
        bc[2 * nt + 1] = bias_s[nt * 8 + tg * 2 + 1];
    }
    float part[8];
#pragma unroll
    for (int j = 0; j < 8; j++) part[j] = 0.f;

    for (int h = 0; h < 8; h++) {
        float acc[2][4][4];
#pragma unroll
        for (int mt = 0; mt < 2; mt++)
#pragma unroll
            for (int nt = 0; nt < 4; nt++)
#pragma unroll
                for (int i = 0; i < 4; i++) acc[mt][nt][i] = 0.f;

#pragma unroll
        for (int s = 0; s < 15; s++) {
            const int kh = s / 5;
            const int kw = s % 5;
            int k0 = s * 16;
            uint32_t a[2][4];
#pragma unroll
            for (int mt = 0; mt < 2; mt++) {
                int mrow = wid * 32 + mt * 16 + arow_l;
                uint32_t addr = as_base + (uint32_t)((h + kh) * A_PLANE
                               + (mrow + kw) * A_RSTR + half * 16);
                LDMATRIX_X4(a[mt][0], a[mt][1], a[mt][2], a[mt][3], addr);
            }
            uint32_t bfr[4][2];
#pragma unroll
            for (int ntp = 0; ntp < 2; ntp++) {
                int nrow = ntp * 16 + (quad >> 1) * 8 + bw;
                uint32_t addr = bs_base + (uint32_t)(nrow * (KP * 2)
                               + (k0 + (quad & 1) * 8) * 2);
                uint32_t r0, r1, r2, r3;
                LDMATRIX_X4(r0, r1, r2, r3, addr);
                bfr[2 * ntp][0] = r0;  bfr[2 * ntp][1] = r1;
                bfr[2 * ntp + 1][0] = r2;  bfr[2 * ntp + 1][1] = r3;
            }
#pragma unroll
            for (int mt = 0; mt < 2; mt++)
#pragma unroll
                for (int nt = 0; nt < 4; nt++)
                    MMA_16816(acc[mt][nt], a[mt], bfr[nt]);
        }

        // bias + relu + maxpool (shfl pair over m rows) -> accumulate
#pragma unroll
        for (int mt = 0; mt < 2; mt++) {
#pragma unroll
            for (int nt = 0; nt < 4; nt++) {
                float v0 = acc[mt][nt][0] + bc[2 * nt];
                float v1 = acc[mt][nt][1] + bc[2 * nt + 1];
                float v2 = acc[mt][nt][2] + bc[2 * nt];
                float v3 = acc[mt][nt][3] + bc[2 * nt + 1];
                float p0 = __shfl_xor_sync(0xffffffffu, v0, 4);
                float p1 = __shfl_xor_sync(0xffffffffu, v1, 4);
                float p2 = __shfl_xor_sync(0xffffffffu, v2, 4);
                float p3 = __shfl_xor_sync(0xffffffffu, v3, 4);
                part[2 * nt]     += fmaxf(fmaxf(v0, p0), 0.f)
                                  + fmaxf(fmaxf(v2, p2), 0.f);
                part[2 * nt + 1] += fmaxf(fmaxf(v1, p1), 0.f)
                                  + fmaxf(fmaxf(v3, p3), 0.f);
            }
        }
    }

    // reduce over gid bits 1,2; lanes 0-3 hold single-counted warp totals
#pragma unroll
    for (int j = 0; j < 8; j++) {
        part[j] += __shfl_xor_sync(0xffffffffu, part[j], 8);
        part[j] += __shfl_xor_sync(0xffffffffu, part[j], 16);
    }
    if (lane < 4) {
#pragma unroll
        for (int nt = 0; nt < 4; nt++) {
            red[wid * 32 + nt * 8 + lane * 2]     = part[2 * nt];
            red[wid * 32 + nt * 8 + lane * 2 + 1] = part[2 * nt + 1];
        }
    }
    __syncthreads();
    if (tid < 32) {
        float tot = red[tid] + red[32 + tid] + red[64 + tid] + red[96 + tid];
        g_part[(b * C2 + tid) * 8 + wt] = tot;
    }
}

// ---------------------------------------------------------------------------
// Kernel 3: head — all weights prefetched to smem, then the dependent chain
// runs on LDS latency only.
// mean -> relu(g@Wg+b) -> LN -> v -> attn_out (attn==1) -> mlp -> out
// ---------------------------------------------------------------------------
// smem float offsets
#define HO_WG   0
#define HO_IPW  2048
#define HO_OW   6144
#define HO_M1W  10240
#define HO_M2W  12288
#define HO_BG   12608
#define HO_GG   12672
#define HO_BEG  12736
#define HO_IPB  12800
#define HO_OB   12864
#define HO_M1B  12928
#define HO_M2B  12960
#define HO_GS   12976
#define HO_A    13008
#define HO_VV   13072
#define HO_AO   13136
#define HO_HH   13200
#define HO_PP   13232
#define HO_RED  13488
#define HEAD_SMEM ((13492) * 4)

__global__ __launch_bounds__(256) void head_kernel(
    const float* __restrict__ wg,  const float* __restrict__ bg,
    const float* __restrict__ gg,  const float* __restrict__ beg,
    const float* __restrict__ ipw, const float* __restrict__ ipb,
    const float* __restrict__ ow,  const float* __restrict__ ob,
    const float* __restrict__ m1w, const float* __restrict__ m1b,
    const float* __restrict__ m2w, const float* __restrict__ m2b,
    float* __restrict__ out)
{
    extern __shared__ __align__(16) float sh[];
    int b    = blockIdx.x;
    int tid  = threadIdx.x;
    int t    = tid & 63;
    int q    = tid >> 6;
    int lane = tid & 31;
    int wid  = tid >> 5;

    // chain head: per-co mean (independent of the prefetch below)
    float gsv = 0.f;
    if (tid < 32) {
        const float4* gp = reinterpret_cast<const float4*>(
            &g_part[(b * C2 + tid) * 8]);
        float4 p0 = gp[0], p1 = gp[1];
        gsv = (p0.x + p0.y + p0.z + p0.w + p1.x + p1.y + p1.z + p1.w)
              * (1.0f / 4096.0f);
    }

    // ---- prefetch all weights/biases into smem ----
#define CP4(off, src, n4)                                                   \
    for (int i = tid; i < (n4); i += 256)                                   \
        reinterpret_cast<float4*>(sh + (off))[i] =                          \
            reinterpret_cast<const float4*>(src)[i];
    CP4(HO_WG,  wg,            512)
    CP4(HO_IPW, ipw + 128 * 64, 1024)
    CP4(HO_OW,  ow,            1024)
    CP4(HO_M1W, m1w,           512)
    CP4(HO_M2W, m2w,           80)
    CP4(HO_BG,  bg,  16)
    CP4(HO_GG,  gg,  16)
    CP4(HO_BEG, beg, 16)
    CP4(HO_IPB, ipb + 128, 16)
    CP4(HO_OB,  ob,  16)
    CP4(HO_M1B, m1b, 8)
#undef CP4
    if (tid < 10) sh[HO_M2B + tid] = m2b[tid];
    if (tid < 32) sh[HO_GS + tid] = gsv;
    __syncthreads();

    float* pp = sh + HO_PP;              // [4][64], aliased [8][32]

    // ---- pre = relu(gs @ wg + bg), k-split 4x8 ----
    {
        float s = 0.f;
#pragma unroll
        for (int i = 0; i < 8; i++) {
            int e = q * 8 + i;
            s += sh[HO_GS + e] * sh[HO_WG + e * 64 + t];
        }
        pp[q * 64 + t] = s;
    }
    __syncthreads();
    float pre = 0.f;
    if (tid < 64) {
        pre = pp[t] + pp[64 + t] + pp[128 + t] + pp[192 + t] + sh[HO_BG + t];
        pre = fmaxf(pre, 0.f);
    }
    // ---- layernorm over 64 ----
    if (tid < 64) {
        float s = pre;
#pragma unroll
        for (int o = 16; o > 0; o >>= 1) s += __shfl_xor_sync(0xffffffffu, s, o);
        if (lane == 0) sh[HO_RED + wid] = s;
    }
    __syncthreads();
    float mean = (sh[HO_RED] + sh[HO_RED + 1]) * (1.0f / 64.0f);
    if (tid < 64) {
        float d = pre - mean;
        float s = d * d;
#pragma unroll
        for (int o = 16; o > 0; o >>= 1) s += __shfl_xor_sync(0xffffffffu, s, o);
        if (lane == 0) sh[HO_RED + 2 + wid] = s;
    }
    __syncthreads();
    if (tid < 64) {
        float var = (sh[HO_RED + 2] + sh[HO_RED + 3]) * (1.0f / 64.0f);
        sh[HO_A + t] = (pre - mean) * rsqrtf(var + 1e-5f) * sh[HO_GG + t]
                       + sh[HO_BEG + t];
    }
    __syncthreads();

    // ---- v = a @ Wv^T + bv, k-split 4x16 ----
    {
        float s = 0.f;
#pragma unroll
        for (int i = 0; i < 16; i++) {
            int e = q * 16 + i;
            s += sh[HO_A + e] * sh[HO_IPW + t * 64 + e];
        }
        pp[q * 64 + t] = s;
    }
    __syncthreads();
    if (tid < 64)
        sh[HO_VV + t] = pp[t] + pp[64 + t] + pp[128 + t] + pp[192 + t]
                        + sh[HO_IPB + t];
    __syncthreads();

    // ---- attn_out = vv @ out_w^T + ob ----
    {
        float s = 0.f;
#pragma unroll
        for (int i = 0; i < 16; i++) {
            int j = q * 16 + i;
            s += sh[HO_VV + j] * sh[HO_OW + t * 64 + j];
        }
        pp[q * 64 + t] = s;
    }
    __syncthreads();
    if (tid < 64)
        sh[HO_AO + t] = pp[t] + pp[64 + t] + pp[128 + t] + pp[192 + t]
                        + sh[HO_OB + t];
    __syncthreads();

    // ---- h = relu(ao @ m1w + b1), 8-way split ----
    {
        int t32 = tid & 31, q2 = wid;
        float s = 0.f;
#pragma unroll
        for (int i = 0; i < 8; i++) {
            int e = q2 * 8 + i;
            s += sh[HO_AO + e] * sh[HO_M1W + e * 32 + t32];
        }
        pp[q2 * 32 + t32] = s;
    }
    __syncthreads();
    if (tid < 32) {
        float s = sh[HO_M1B + tid];
#pragma unroll
        for (int g2 = 0; g2 < 8; g2++) s += pp[g2 * 32 + tid];
        sh[HO_HH + tid] = fmaxf(s, 0.f);
    }
    __syncthreads();

    if (tid < 10) {
        float o = sh[HO_M2B + tid];
#pragma unroll
        for (int m = 0; m < 32; m++)
            o += sh[HO_HH + m] * sh[HO_M2W + m * 10 + tid];
        out[b * 10 + tid] = o;
    }
}

// ---------------------------------------------------------------------------
extern "C" void kernel_launch(void* const* d_in, const int* in_sizes, int n_in,
                              void* d_out, int out_size)
{
    const float* x    = (const float*)d_in[0];
    const float* c1w  = (const float*)d_in[6];
    const float* c1b  = (const float*)d_in[7];
    const float* c2w  = (const float*)d_in[8];
    const float* c2b  = (const float*)d_in[9];
    const float* wg   = (const float*)d_in[10];
    const float* bg   = (const float*)d_in[11];
    const float* gg   = (const float*)d_in[12];
    const float* beg  = (const float*)d_in[13];
    const float* ipw  = (const float*)d_in[14];
    const float* ipb  = (const float*)d_in[15];
    const float* ow   = (const float*)d_in[16];
    const float* ob   = (const float*)d_in[17];
    const float* m1w  = (const float*)d_in[18];
    const float* m1b  = (const float*)d_in[19];
    const float* m2w  = (const float*)d_in[20];
    const float* m2b  = (const float*)d_in[21];
    float* out = (float*)d_out;

    cudaFuncSetAttribute(conv2_mma_kernel,
                         cudaFuncAttributeMaxDynamicSharedMemorySize, 81920);
    cudaFuncSetAttribute(head_kernel,
                         cudaFuncAttributeMaxDynamicSharedMemorySize, HEAD_SMEM);

    dim3 g1(8, 65);                      // y==64 -> fused w2 prep
    conv1_pool_kernel<<<g1, 256>>>(x, c1w, c1b, c2w);

    dim3 g2(8, B_);
    conv2_mma_kernel<<<g2, 128, 81920>>>(c2b);

    head_kernel<<<B_, 256, HEAD_SMEM>>>(wg, bg, gg, beg, ipw, ipb, ow, ob,
                                        m1w, m1b, m2w, m2b, out);
}

// round 12
// speedup vs baseline: 4.9561x; 1.6834x over previous
#include <cuda_runtime.h>
#include <cuda_bf16.h>
#include <cstdint>

// ---------------------------------------------------------------------------
// LocalGlobalCrossAttentionModel — round 11
// softmax over singleton axis == 1.0 -> shapelet/local branch dead code.
// conv1+pool (fp32, broadcast-LDS mapping, 4096-block grid, fused w2 prep) ->
// conv2+pool (mma.sync bf16, shifted-view A, 8 warps h-split, all h per
// block) -> head (all weights prefetched to smem).
// ---------------------------------------------------------------------------

#define B_  64
#define H_  8
#define W1_ 2048
#define W1P 1024
#define C1  16
#define C2  32
#define KK  240              // 15 * 16
#define KP  248              // padded K for B (496B stride, conflict-free)

// conv1 output, bf16, [b][h][w][ci] (ci contiguous -> 32B granules)
__device__ __nv_bfloat16 g_h1b[B_ * H_ * W1P * C1];
// conv2 weights as B^T row-major [co][k], bf16
__device__ __nv_bfloat16 g_w2b[C2 * KK];
// per-(b,co,wt) pooled partial sums (summed over h inside conv2)
__device__ float g_part[B_ * C2 * 8];

__device__ __forceinline__ uint32_t smem_u32(const void* p) {
    uint32_t a;
    asm("{ .reg .u64 t; cvta.to.shared.u64 t, %1; cvt.u32.u64 %0, t; }"
        : "=r"(a) : "l"(p));
    return a;
}

#define LDMATRIX_X4(r0, r1, r2, r3, addr)                                   \
    asm volatile("ldmatrix.sync.aligned.m8n8.x4.shared.b16 "                \
                 "{%0, %1, %2, %3}, [%4];"                                  \
                 : "=r"(r0), "=r"(r1), "=r"(r2), "=r"(r3) : "r"(addr))

#define MMA_16816(c, a, b)                                                  \
    asm volatile("mma.sync.aligned.m16n8k16.row.col.f32.bf16.bf16.f32 "     \
                 "{%0, %1, %2, %3}, {%4, %5, %6, %7}, {%8, %9}, "           \
                 "{%0, %1, %2, %3};"                                        \
                 : "+f"((c)[0]), "+f"((c)[1]), "+f"((c)[2]), "+f"((c)[3])   \
                 : "r"((a)[0]), "r"((a)[1]), "r"((a)[2]), "r"((a)[3]),      \
                   "r"((b)[0]), "r"((b)[1]))

// ---------------------------------------------------------------------------
// Kernel 1: conv1 (1->16ch, 3x5, pad 1,2) + relu + maxpool(w/2).
// Grid (wt=8, h=8, bz=65); bz==64 -> fused conv2-weight prep.
// Thread mapping co = tid&15, ws = tid>>4: the 16 co-threads of a ws group
// read identical x addresses -> all compute LDS are warp broadcasts.
// ---------------------------------------------------------------------------
__global__ __launch_bounds__(256) void conv1_pool_kernel(
    const float* __restrict__ x,
    const float* __restrict__ w1,
    const float* __restrict__ b1,
    const float* __restrict__ w2)
{
    int tid = threadIdx.x;

    if (blockIdx.z == 64) {               // fused weight-prep branch
        if (blockIdx.x != 0 || blockIdx.y != 0) return;
        for (int idx = tid; idx < C2 * 15 * C1; idx += 256) {
            int ci   = idx & 15;
            int khkw = (idx >> 4) % 15;
            int co   = idx / (15 * 16);
            g_w2b[co * KK + khkw * 16 + ci] =
                __float2bfloat16(w2[(co * 16 + ci) * 15 + khkw]);
        }
        return;
    }

    int b   = blockIdx.z;
    int h   = blockIdx.y;
    int wp0 = blockIdx.x * 128;
    int c0  = wp0 * 2;

    __shared__ __align__(16) float xs[3][264];
    __shared__ __align__(16) __nv_bfloat16 stg[128][16];

    for (int idx = tid; idx < 3 * 260; idx += 256) {
        int r = idx / 260;
        int j = idx - r * 260;
        int hr = h - 1 + r;
        int c  = c0 - 2 + j;
        float v = 0.f;
        if (hr >= 0 && hr < H_ && c >= 0 && c < W1_)
            v = x[(b * H_ + hr) * W1_ + c];
        xs[r][j] = v;
    }

    int co = tid & 15;            // fast index -> broadcast LDS
    int ws = tid >> 4;
    int base = ws * 16;

    float wgt[15];
#pragma unroll
    for (int i = 0; i < 15; i++) wgt[i] = __ldg(&w1[co * 15 + i]);
    float bias = __ldg(&b1[co]);
    __syncthreads();

    float acc[16];
#pragma unroll
    for (int j = 0; j < 16; j++) acc[j] = bias;

#pragma unroll
    for (int kh = 0; kh < 3; kh++) {
        float r_[20];
        const float4* rp = reinterpret_cast<const float4*>(&xs[kh][base]);
#pragma unroll
        for (int q = 0; q < 5; q++) {
            float4 f = rp[q];   // broadcast across the 16 co threads
            r_[4 * q + 0] = f.x; r_[4 * q + 1] = f.y;
            r_[4 * q + 2] = f.z; r_[4 * q + 3] = f.w;
        }
#pragma unroll
        for (int kw = 0; kw < 5; kw++) {
            float w = wgt[kh * 5 + kw];
#pragma unroll
            for (int j = 0; j < 16; j++)
                acc[j] += w * r_[j + kw];
        }
    }

#pragma unroll
    for (int p = 0; p < 8; p++)
        stg[ws * 8 + p][co] =
            __float2bfloat16(fmaxf(fmaxf(acc[2 * p], acc[2 * p + 1]), 0.f));
    __syncthreads();

    uint4 v = reinterpret_cast<const uint4*>(stg)[tid];
    reinterpret_cast<uint4*>(
        &g_h1b[((size_t)(b * H_ + h) * W1P + wp0) * C1])[tid] = v;
}

// ---------------------------------------------------------------------------
// Kernel 2: conv2 via mma.sync, shifted-view A, 256 threads.
// 10 h-planes of [132 w-rows][16 ci] bf16 at 48B stride loaded once; warps
// 0-3 process h 0-3, warps 4-7 process h 4-7 (2x latency hiding, same smem).
// Pooled partials accumulate in registers across each warp's 4 h rows.
// ---------------------------------------------------------------------------
#define A_ROWS   136
#define A_RSTR   48
#define A_PLANE  (A_ROWS * A_RSTR)                  // 6528
#define SA_BYTES (10 * A_PLANE)                     // 65280
#define BS_OFF   SA_BYTES
#define BS_BYTES (C2 * KP * 2)                      // 15872
#define BIAS_OFF (BS_OFF + BS_BYTES)                // 81152
#define RED_OFF  (BIAS_OFF + 128)                   // 81280
#define C2_SMEM  (RED_OFF + 8 * 32 * 4 + 64)        // 82368

__global__ __launch_bounds__(256) void conv2_mma_kernel(
    const float* __restrict__ b2)
{
    extern __shared__ __align__(16) char sm2[];
    __nv_bfloat16* Bs = (__nv_bfloat16*)(sm2 + BS_OFF);
    float* bias_s = (float*)(sm2 + BIAS_OFF);
    float* red    = (float*)(sm2 + RED_OFF);

    int b  = blockIdx.y;
    int wt = blockIdx.x;
    int wbase = wt * 128;
    int tid  = threadIdx.x;
    int wid  = tid >> 5;
    int lane = tid & 31;
    int hg   = wid >> 2;          // h group: 0 -> h 0..3, 1 -> h 4..7
    int wq   = wid & 3;           // m-range within 128 rows

    if (tid < 32) bias_s[tid] = b2[tid];

    // ---- fill 10 A planes (input rows -1..8), rows r -> w = wbase-2+r ----
#pragma unroll
    for (int p = 0; p < 10; p++) {
        int row = p - 1;
        for (int r = tid; r < 132; r += 256) {
            int w = wbase - 2 + r;
            uint4 h0 = make_uint4(0, 0, 0, 0), h1 = make_uint4(0, 0, 0, 0);
            if (row >= 0 && row < H_ && w >= 0 && w < W1P) {
                const uint4* pg = reinterpret_cast<const uint4*>(
                    &g_h1b[((size_t)(b * H_ + row) * W1P + w) * C1]);
                h0 = pg[0]; h1 = pg[1];
            }
            char* dst = sm2 + p * A_PLANE + r * A_RSTR;
            reinterpret_cast<uint4*>(dst)[0] = h0;
            reinterpret_cast<uint4*>(dst)[1] = h1;
        }
    }
    // ---- copy B^T (32 rows x 240 -> stride 248), once per block ----
    for (int idx = tid; idx < C2 * 30; idx += 256) {
        int r = idx / 30;
        int c16 = idx % 30;
        reinterpret_cast<uint4*>((char*)&Bs[r * KP])[c16] =
            reinterpret_cast<const uint4*>((char*)&g_w2b[r * KK])[c16];
    }
    __syncthreads();

    uint32_t as_base = smem_u32(sm2);
    uint32_t bs_base = smem_u32(Bs);
    int half = lane >> 4;
    int arow_l = lane & 15;
    int quad = lane >> 3;
    int bw   = lane & 7;
    int tg   = lane & 3;

    float bc[8];
#pragma unroll
    for (int nt = 0; nt < 4; nt++) {
        bc[2 * nt]     = bias_s[nt * 8 + tg * 2];
        bc[2 * nt + 1] = bias_s[nt * 8 + tg * 2 + 1];
    }
    float part[8];
#pragma unroll
    for (int j = 0; j < 8; j++) part[j] = 0.f;

#pragma unroll
    for (int hi = 0; hi < 4; hi++) {
        int h = hg * 4 + hi;
        float acc[2][4][4];
#pragma unroll
        for (int mt = 0; mt < 2; mt++)
#pragma unroll
            for (int nt = 0; nt < 4; nt++)
#pragma unroll
                for (int i = 0; i < 4; i++) acc[mt][nt][i] = 0.f;

#pragma unroll
        for (int s = 0; s < 15; s++) {
            const int kh = s / 5;
            const int kw = s % 5;
            int k0 = s * 16;
            uint32_t a[2][4];
#pragma unroll
            for (int mt = 0; mt < 2; mt++) {
                int mrow = wq * 32 + mt * 16 + arow_l;
                uint32_t addr = as_base + (uint32_t)((h + kh) * A_PLANE
                               + (mrow + kw) * A_RSTR + half * 16);
                LDMATRIX_X4(a[mt][0], a[mt][1], a[mt][2], a[mt][3], addr);
            }
            uint32_t bfr[4][2];
#pragma unroll
            for (int ntp = 0; ntp < 2; ntp++) {
                int nrow = ntp * 16 + (quad >> 1) * 8 + bw;
                uint32_t addr = bs_base + (uint32_t)(nrow * (KP * 2)
                               + (k0 + (quad & 1) * 8) * 2);
                uint32_t r0, r1, r2, r3;
                LDMATRIX_X4(r0, r1, r2, r3, addr);
                bfr[2 * ntp][0] = r0;  bfr[2 * ntp][1] = r1;
                bfr[2 * ntp + 1][0] = r2;  bfr[2 * ntp + 1][1] = r3;
            }
#pragma unroll
            for (int mt = 0; mt < 2; mt++)
#pragma unroll
                for (int nt = 0; nt < 4; nt++)
                    MMA_16816(acc[mt][nt], a[mt], bfr[nt]);
        }

        // bias + relu + maxpool (shfl pair over m rows) -> accumulate
#pragma unroll
        for (int mt = 0; mt < 2; mt++) {
#pragma unroll
            for (int nt = 0; nt < 4; nt++) {
                float v0 = acc[mt][nt][0] + bc[2 * nt];
                float v1 = acc[mt][nt][1] + bc[2 * nt + 1];
                float v2 = acc[mt][nt][2] + bc[2 * nt];
                float v3 = acc[mt][nt][3] + bc[2 * nt + 1];
                float p0 = __shfl_xor_sync(0xffffffffu, v0, 4);
                float p1 = __shfl_xor_sync(0xffffffffu, v1, 4);
                float p2 = __shfl_xor_sync(0xffffffffu, v2, 4);
                float p3 = __shfl_xor_sync(0xffffffffu, v3, 4);
                part[2 * nt]     += fmaxf(fmaxf(v0, p0), 0.f)
                                  + fmaxf(fmaxf(v2, p2), 0.f);
                part[2 * nt + 1] += fmaxf(fmaxf(v1, p1), 0.f)
                                  + fmaxf(fmaxf(v3, p3), 0.f);
            }
        }
    }

    // reduce over gid bits 1,2; lanes 0-3 hold single-counted warp totals
#pragma unroll
    for (int j = 0; j < 8; j++) {
        part[j] += __shfl_xor_sync(0xffffffffu, part[j], 8);
        part[j] += __shfl_xor_sync(0xffffffffu, part[j], 16);
    }
    if (lane < 4) {
#pragma unroll
        for (int nt = 0; nt < 4; nt++) {
            red[wid * 32 + nt * 8 + lane * 2]     = part[2 * nt];
            red[wid * 32 + nt * 8 + lane * 2 + 1] = part[2 * nt + 1];
        }
    }
    __syncthreads();
    if (tid < 32) {
        float tot = 0.f;
#pragma unroll
        for (int wdi = 0; wdi < 8; wdi++) tot += red[wdi * 32 + tid];
        g_part[(b * C2 + tid) * 8 + wt] = tot;
    }
}

// ---------------------------------------------------------------------------
// Kernel 3: head — all weights prefetched to smem, then the dependent chain
// runs on LDS latency only.
// ---------------------------------------------------------------------------
#define HO_WG   0
#define HO_IPW  2048
#define HO_OW   6144
#define HO_M1W  10240
#define HO_M2W  12288
#define HO_BG   12608
#define HO_GG   12672
#define HO_BEG  12736
#define HO_IPB  12800
#define HO_OB   12864
#define HO_M1B  12928
#define HO_M2B  12960
#define HO_GS   12976
#define HO_A    13008
#define HO_VV   13072
#define HO_AO   13136
#define HO_HH   13200
#define HO_PP   13232
#define HO_RED  13488
#define HEAD_SMEM ((13492) * 4)

__global__ __launch_bounds__(256) void head_kernel(
    const float* __restrict__ wg,  const float* __restrict__ bg,
    const float* __restrict__ gg,  const float* __restrict__ beg,
    const float* __restrict__ ipw, const float* __restrict__ ipb,
    const float* __restrict__ ow,  const float* __restrict__ ob,
    const float* __restrict__ m1w, const float* __restrict__ m1b,
    const float* __restrict__ m2w, const float* __restrict__ m2b,
    float* __restrict__ out)
{
    extern __shared__ __align__(16) float sh[];
    int b    = blockIdx.x;
    int tid  = threadIdx.x;
    int t    = tid & 63;
    int q    = tid >> 6;
    int lane = tid & 31;
    int wid  = tid >> 5;

    float gsv = 0.f;
    if (tid < 32) {
        const float4* gp = reinterpret_cast<const float4*>(
            &g_part[(b * C2 + tid) * 8]);
        float4 p0 = gp[0], p1 = gp[1];
        gsv = (p0.x + p0.y + p0.z + p0.w + p1.x + p1.y + p1.z + p1.w)
              * (1.0f / 4096.0f);
    }

#define CP4(off, src, n4)                                                   \
    for (int i = tid; i < (n4); i += 256)                                   \
        reinterpret_cast<float4*>(sh + (off))[i] =                          \
            reinterpret_cast<const float4*>(src)[i];
    CP4(HO_WG,  wg,            512)
    CP4(HO_IPW, ipw + 128 * 64, 1024)
    CP4(HO_OW,  ow,            1024)
    CP4(HO_M1W, m1w,           512)
    CP4(HO_M2W, m2w,           80)
    CP4(HO_BG,  bg,  16)
    CP4(HO_GG,  gg,  16)
    CP4(HO_BEG, beg, 16)
    CP4(HO_IPB, ipb + 128, 16)
    CP4(HO_OB,  ob,  16)
    CP4(HO_M1B, m1b, 8)
#undef CP4
    if (tid < 10) sh[HO_M2B + tid] = m2b[tid];
    if (tid < 32) sh[HO_GS + tid] = gsv;
    __syncthreads();

    float* pp = sh + HO_PP;

    {
        float s = 0.f;
#pragma unroll
        for (int i = 0; i < 8; i++) {
            int e = q * 8 + i;
            s += sh[HO_GS + e] * sh[HO_WG + e * 64 + t];
        }
        pp[q * 64 + t] = s;
    }
    __syncthreads();
    float pre = 0.f;
    if (tid < 64) {
        pre = pp[t] + pp[64 + t] + pp[128 + t] + pp[192 + t] + sh[HO_BG + t];
        pre = fmaxf(pre, 0.f);
    }
    if (tid < 64) {
        float s = pre;
#pragma unroll
        for (int o = 16; o > 0; o >>= 1) s += __shfl_xor_sync(0xffffffffu, s, o);
        if (lane == 0) sh[HO_RED + wid] = s;
    }
    __syncthreads();
    float mean = (sh[HO_RED] + sh[HO_RED + 1]) * (1.0f / 64.0f);
    if (tid < 64) {
        float d = pre - mean;
        float s = d * d;
#pragma unroll
        for (int o = 16; o > 0; o >>= 1) s += __shfl_xor_sync(0xffffffffu, s, o);
        if (lane == 0) sh[HO_RED + 2 + wid] = s;
    }
    __syncthreads();
    if (tid < 64) {
        float var = (sh[HO_RED + 2] + sh[HO_RED + 3]) * (1.0f / 64.0f);
        sh[HO_A + t] = (pre - mean) * rsqrtf(var + 1e-5f) * sh[HO_GG + t]
                       + sh[HO_BEG + t];
    }
    __syncthreads();

    {
        float s = 0.f;
#pragma unroll
        for (int i = 0; i < 16; i++) {
            int e = q * 16 + i;
            s += sh[HO_A + e] * sh[HO_IPW + t * 64 + e];
        }
        pp[q * 64 + t] = s;
    }
    __syncthreads();
    if (tid < 64)
        sh[HO_VV + t] = pp[t] + pp[64 + t] + pp[128 + t] + pp[192 + t]
                        + sh[HO_IPB + t];
    __syncthreads();

    {
        float s = 0.f;
#pragma unroll
        for (int i = 0; i < 16; i++) {
            int j = q * 16 + i;
            s += sh[HO_VV + j] * sh[HO_OW + t * 64 + j];
        }
        pp[q * 64 + t] = s;
    }
    __syncthreads();
    if (tid < 64)
        sh[HO_AO + t] = pp[t] + pp[64 + t] + pp[128 + t] + pp[192 + t]
                        + sh[HO_OB + t];
    __syncthreads();

    {
        int t32 = tid & 31, q2 = wid;
        float s = 0.f;
#pragma unroll
        for (int i = 0; i < 8; i++) {
            int e = q2 * 8 + i;
            s += sh[HO_AO + e] * sh[HO_M1W + e * 32 + t32];
        }
        pp[q2 * 32 + t32] = s;
    }
    __syncthreads();
    if (tid < 32) {
        float s = sh[HO_M1B + tid];
#pragma unroll
        for (int g2 = 0; g2 < 8; g2++) s += pp[g2 * 32 + tid];
        sh[HO_HH + tid] = fmaxf(s, 0.f);
    }
    __syncthreads();

    if (tid < 10) {
        float o = sh[HO_M2B + tid];
#pragma unroll
        for (int m = 0; m < 32; m++)
            o += sh[HO_HH + m] * sh[HO_M2W + m * 10 + tid];
        out[b * 10 + tid] = o;
    }
}

// ---------------------------------------------------------------------------
extern "C" void kernel_launch(void* const* d_in, const int* in_sizes, int n_in,
                              void* d_out, int out_size)
{
    const float* x    = (const float*)d_in[0];
    const float* c1w  = (const float*)d_in[6];
    const float* c1b  = (const float*)d_in[7];
    const float* c2w  = (const float*)d_in[8];
    const float* c2b  = (const float*)d_in[9];
    const float* wg   = (const float*)d_in[10];
    const float* bg   = (const float*)d_in[11];
    const float* gg   = (const float*)d_in[12];
    const float* beg  = (const float*)d_in[13];
    const float* ipw  = (const float*)d_in[14];
    const float* ipb  = (const float*)d_in[15];
    const float* ow   = (const float*)d_in[16];
    const float* ob   = (const float*)d_in[17];
    const float* m1w  = (const float*)d_in[18];
    const float* m1b  = (const float*)d_in[19];
    const float* m2w  = (const float*)d_in[20];
    const float* m2b  = (const float*)d_in[21];
    float* out = (float*)d_out;

    cudaFuncSetAttribute(conv2_mma_kernel,
                         cudaFuncAttributeMaxDynamicSharedMemorySize, C2_SMEM);
    cudaFuncSetAttribute(head_kernel,
                         cudaFuncAttributeMaxDynamicSharedMemorySize, HEAD_SMEM);

    dim3 g1(8, 8, 65);                   // z==64 -> fused w2 prep
    conv1_pool_kernel<<<g1, 256>>>(x, c1w, c1b, c2w);

    dim3 g2(8, B_);
    conv2_mma_kernel<<<g2, 256, C2_SMEM>>>(c2b);

    head_kernel<<<B_, 256, HEAD_SMEM>>>(wg, bg, gg, beg, ipw, ipb, ow, ob,
                                        m1w, m1b, m2w, m2b, out);
}

// round 15
// speedup vs baseline: 5.0228x; 1.0135x over previous
#include <cuda_runtime.h>
#include <cuda_bf16.h>
#include <cstdint>

// ---------------------------------------------------------------------------
// LocalGlobalCrossAttentionModel — round 14
// softmax over singleton axis == 1.0 -> shapelet/local branch dead code.
// FUSED conv1+pool+conv2+pool kernel: conv1 (fp32, broadcast-LDS) writes
// pooled bf16 output directly into the smem A-planes read by conv2's
// mma.sync path (shifted-view, 8 warps h-split). R13 misalignment fixed:
// xs tile base = 2*wbase-8 (16B aligned), conv reads 6 aligned float4 and
// indexes the window at +2. Head kernel unchanged (smem-prefetched).
// ---------------------------------------------------------------------------

#define B_  64
#define H_  8
#define W1_ 2048
#define W1P 1024
#define C1  16
#define C2  32
#define KK  240              // 15 * 16
#define KP  248              // padded K for B (496B stride, conflict-free)

// per-(b,co,wt) pooled partial sums (summed over h inside fused kernel)
__device__ float g_part[B_ * C2 * 8];

__device__ __forceinline__ uint32_t smem_u32(const void* p) {
    uint32_t a;
    asm("{ .reg .u64 t; cvta.to.shared.u64 t, %1; cvt.u32.u64 %0, t; }"
        : "=r"(a) : "l"(p));
    return a;
}

#define LDMATRIX_X4(r0, r1, r2, r3, addr)                                   \
    asm volatile("ldmatrix.sync.aligned.m8n8.x4.shared.b16 "                \
                 "{%0, %1, %2, %3}, [%4];"                                  \
                 : "=r"(r0), "=r"(r1), "=r"(r2), "=r"(r3) : "r"(addr))

#define MMA_16816(c, a, b)                                                  \
    asm volatile("mma.sync.aligned.m16n8k16.row.col.f32.bf16.bf16.f32 "     \
                 "{%0, %1, %2, %3}, {%4, %5, %6, %7}, {%8, %9}, "           \
                 "{%0, %1, %2, %3};"                                        \
                 : "+f"((c)[0]), "+f"((c)[1]), "+f"((c)[2]), "+f"((c)[3])   \
                 : "r"((a)[0]), "r"((a)[1]), "r"((a)[2]), "r"((a)[3]),      \
                   "r"((b)[0]), "r"((b)[1]))

// ---------------------------------------------------------------------------
// smem layout (bytes)
// ---------------------------------------------------------------------------
#define A_ROWS   136
#define A_RSTR   48
#define A_PLANE  (A_ROWS * A_RSTR)                  // 6528
#define SA_BYTES (10 * A_PLANE)                     // 65280
#define BS_OFF   SA_BYTES                           // 65280
#define BS_BYTES (C2 * KP * 2)                      // 15872
#define BIAS_OFF (BS_OFF + BS_BYTES)                // 81152
#define RED_OFF  (BIAS_OFF + 128)                   // 81280
#define XS_OFF   (RED_OFF + 1024)                   // 82304
#define XS_ROWF  272                                // floats per x row
#define XS_BYTES (10 * XS_ROWF * 4)                 // 10880
#define FU_SMEM  (XS_OFF + XS_BYTES)                // 93184

// ---------------------------------------------------------------------------
// Fused kernel. Grid (wt=8, b=64), 256 threads.
// xs row p (= x row p-1) holds x cols [2*wbase-8, 2*wbase+264): col g at
// local index g - (2*wbase-8). All float4 accesses 16B-aligned.
// ---------------------------------------------------------------------------
__global__ __launch_bounds__(256) void fused_conv_kernel(
    const float* __restrict__ x,
    const float* __restrict__ w1,
    const float* __restrict__ b1,
    const float* __restrict__ w2,
    const float* __restrict__ b2)
{
    extern __shared__ __align__(16) char sm2[];
    __nv_bfloat16* Bs = (__nv_bfloat16*)(sm2 + BS_OFF);
    float* bias_s = (float*)(sm2 + BIAS_OFF);
    float* red    = (float*)(sm2 + RED_OFF);
    float* xs     = (float*)(sm2 + XS_OFF);

    int b  = blockIdx.y;
    int wt = blockIdx.x;
    int wbase = wt * 128;
    int tid  = threadIdx.x;
    int wid  = tid >> 5;
    int lane = tid & 31;

    // ---- fill x tile: base col xg0 = 2*wbase-8 (multiple of 4) ----
    int xg0 = 2 * wbase - 8;
    for (int idx = tid; idx < 10 * 68; idx += 256) {
        int p  = idx / 68;
        int q4 = idx - p * 68;
        int row = p - 1;
        float4 v = make_float4(0.f, 0.f, 0.f, 0.f);
        if (row >= 0 && row < H_) {
            int g = xg0 + q4 * 4;                    // multiple of 4
            const float* xr = &x[(b * H_ + row) * W1_];
            if (g >= 0 && g + 3 < W1_) {
                v = *reinterpret_cast<const float4*>(&xr[g]);
            } else {
                float e[4];
#pragma unroll
                for (int k = 0; k < 4; k++)
                    e[k] = (g + k >= 0 && g + k < W1_) ? xr[g + k] : 0.f;
                v = make_float4(e[0], e[1], e[2], e[3]);
            }
        }
        reinterpret_cast<float4*>(&xs[p * XS_ROWF])[q4] = v;
    }
    // ---- zero A planes 0 and 9 (h = -1, 8); A_PLANE = 408 uint4 ----
    for (int idx = tid; idx < 2 * 408; idx += 256) {
        int pl = (idx < 408) ? 0 : 9;
        int j  = idx - (pl ? 408 : 0);
        reinterpret_cast<uint4*>(sm2 + pl * A_PLANE)[j] =
            make_uint4(0, 0, 0, 0);
    }
    // ---- convert conv2 weights into Bs[co][k], k = (kh*5+kw)*16 + ci ----
    for (int idx = tid; idx < C2 * 15 * C1; idx += 256) {
        int ci   = idx & 15;
        int khkw = (idx >> 4) % 15;
        int co   = idx / 240;
        Bs[co * KP + khkw * 16 + ci] =
            __float2bfloat16(w2[(co * 16 + ci) * 15 + khkw]);
    }
    if (tid < 32) bias_s[tid] = b2[tid];

    // ---- per-thread conv1 weights (co = tid&15 -> broadcast LDS) ----
    int co1 = tid & 15;
    int ws  = tid >> 4;
    float wgt[15];
#pragma unroll
    for (int i = 0; i < 15; i++) wgt[i] = __ldg(&w1[co1 * 15 + i]);
    float bias1 = __ldg(&b1[co1]);
    __syncthreads();

    // ---- conv1 + relu + maxpool into planes 1..8 ----
    // pooled row r covers conv cols 2*wsrc, 2*wsrc+1, wsrc = wbase-2+r;
    // x cols needed for rows r0..r0+7: [2*wbase+16ws-6, 2*wbase+16ws+15+6)
    // -> local idx [16ws+2, 16ws+24) -> 6 aligned float4 from 16ws.
    for (int h = 0; h < 8; h++) {
        char* plane = sm2 + (h + 1) * A_PLANE;
        int r0 = ws * 8;
        float acc[16];
#pragma unroll
        for (int j = 0; j < 16; j++) acc[j] = bias1;
#pragma unroll
        for (int kh = 0; kh < 3; kh++) {
            float buf[24];
            const float4* rp = reinterpret_cast<const float4*>(
                &xs[(h + kh) * XS_ROWF + 16 * ws]);
#pragma unroll
            for (int q = 0; q < 6; q++) {
                float4 f = rp[q];   // broadcast across the 16 co threads
                buf[4 * q + 0] = f.x; buf[4 * q + 1] = f.y;
                buf[4 * q + 2] = f.z; buf[4 * q + 3] = f.w;
            }
#pragma unroll
            for (int kw = 0; kw < 5; kw++) {
                float w = wgt[kh * 5 + kw];
#pragma unroll
                for (int j = 0; j < 16; j++)
                    acc[j] += w * buf[2 + j + kw];
            }
        }
#pragma unroll
        for (int p = 0; p < 8; p++) {
            int r = r0 + p;
            int w = wbase - 2 + r;
            float v = fmaxf(fmaxf(acc[2 * p], acc[2 * p + 1]), 0.f);
            if (w < 0 || w >= W1P) v = 0.f;
            *reinterpret_cast<__nv_bfloat16*>(plane + r * A_RSTR + co1 * 2) =
                __float2bfloat16(v);
        }
        // tail rows 128..131 (ws 0..3): window local base 258 + 2*ws
        if (ws < 4) {
            int r = 128 + ws;
            int w = wbase - 2 + r;
            const int lx = 258 + 2 * ws;
            float a0 = bias1, a1 = bias1;
#pragma unroll
            for (int kh = 0; kh < 3; kh++) {
                const float* xr = &xs[(h + kh) * XS_ROWF + lx];
#pragma unroll
                for (int kw = 0; kw < 5; kw++) {
                    float wv = wgt[kh * 5 + kw];
                    a0 += wv * xr[kw];
                    a1 += wv * xr[kw + 1];
                }
            }
            float v = fmaxf(fmaxf(a0, a1), 0.f);
            if (w < 0 || w >= W1P) v = 0.f;
            *reinterpret_cast<__nv_bfloat16*>(plane + r * A_RSTR + co1 * 2) =
                __float2bfloat16(v);
        }
    }
    __syncthreads();

    // ---- conv2 mma phase (structure of round 12) ----
    uint32_t as_base = smem_u32(sm2);
    uint32_t bs_base = smem_u32(Bs);
    int hg   = wid >> 2;          // h group: 0 -> h 0..3, 1 -> h 4..7
    int wq   = wid & 3;           // m-range within 128 rows
    int half = lane >> 4;
    int arow_l = lane & 15;
    int quad = lane >> 3;
    int bw   = lane & 7;
    int tg   = lane & 3;

    float bc[8];
#pragma unroll
    for (int nt = 0; nt < 4; nt++) {
        bc[2 * nt]     = bias_s[nt * 8 + tg * 2];
        bc[2 * nt + 1] = bias_s[nt * 8 + tg * 2 + 1];
    }
    float part[8];
#pragma unroll
    for (int j = 0; j < 8; j++) part[j] = 0.f;

#pragma unroll
    for (int hi = 0; hi < 4; hi++) {
        int h = hg * 4 + hi;
        float acc[2][4][4];
#pragma unroll
        for (int mt = 0; mt < 2; mt++)
#pragma unroll
            for (int nt = 0; nt < 4; nt++)
#pragma unroll
                for (int i = 0; i < 4; i++) acc[mt][nt][i] = 0.f;

#pragma unroll
        for (int s = 0; s < 15; s++) {
            const int kh = s / 5;
            const int kw = s % 5;
            int k0 = s * 16;
            uint32_t a[2][4];
#pragma unroll
            for (int mt = 0; mt < 2; mt++) {
                int mrow = wq * 32 + mt * 16 + arow_l;
                uint32_t addr = as_base + (uint32_t)((h + kh) * A_PLANE
                               + (mrow + kw) * A_RSTR + half * 16);
                LDMATRIX_X4(a[mt][0], a[mt][1], a[mt][2], a[mt][3], addr);
            }
            uint32_t bfr[4][2];
#pragma unroll
            for (int ntp = 0; ntp < 2; ntp++) {
                int nrow = ntp * 16 + (quad >> 1) * 8 + bw;
                uint32_t addr = bs_base + (uint32_t)(nrow * (KP * 2)
                               + (k0 + (quad & 1) * 8) * 2);
                uint32_t r0r, r1r, r2r, r3r;
                LDMATRIX_X4(r0r, r1r, r2r, r3r, addr);
                bfr[2 * ntp][0] = r0r;  bfr[2 * ntp][1] = r1r;
                bfr[2 * ntp + 1][0] = r2r;  bfr[2 * ntp + 1][1] = r3r;
            }
#pragma unroll
            for (int mt = 0; mt < 2; mt++)
#pragma unroll
                for (int nt = 0; nt < 4; nt++)
                    MMA_16816(acc[mt][nt], a[mt], bfr[nt]);
        }

        // bias + relu + maxpool (shfl pair over m rows) -> accumulate
#pragma unroll
        for (int mt = 0; mt < 2; mt++) {
#pragma unroll
            for (int nt = 0; nt < 4; nt++) {
                float v0 = acc[mt][nt][0] + bc[2 * nt];
                float v1 = acc[mt][nt][1] + bc[2 * nt + 1];
                float v2 = acc[mt][nt][2] + bc[2 * nt];
                float v3 = acc[mt][nt][3] + bc[2 * nt + 1];
                float p0 = __shfl_xor_sync(0xffffffffu, v0, 4);
                float p1 = __shfl_xor_sync(0xffffffffu, v1, 4);
                float p2 = __shfl_xor_sync(0xffffffffu, v2, 4);
                float p3 = __shfl_xor_sync(0xffffffffu, v3, 4);
                part[2 * nt]     += fmaxf(fmaxf(v0, p0), 0.f)
                                  + fmaxf(fmaxf(v2, p2), 0.f);
                part[2 * nt + 1] += fmaxf(fmaxf(v1, p1), 0.f)
                                  + fmaxf(fmaxf(v3, p3), 0.f);
            }
        }
    }

    // reduce over gid bits 1,2; lanes 0-3 hold single-counted warp totals
#pragma unroll
    for (int j = 0; j < 8; j++) {
        part[j] += __shfl_xor_sync(0xffffffffu, part[j], 8);
        part[j] += __shfl_xor_sync(0xffffffffu, part[j], 16);
    }
    if (lane < 4) {
#pragma unroll
        for (int nt = 0; nt < 4; nt++) {
            red[wid * 32 + nt * 8 + lane * 2]     = part[2 * nt];
            red[wid * 32 + nt * 8 + lane * 2 + 1] = part[2 * nt + 1];
        }
    }
    __syncthreads();
    if (tid < 32) {
        float tot = 0.f;
#pragma unroll
        for (int wdi = 0; wdi < 8; wdi++) tot += red[wdi * 32 + tid];
        g_part[(b * C2 + tid) * 8 + wt] = tot;
    }
}

// ---------------------------------------------------------------------------
// Head kernel — all weights prefetched to smem (unchanged from round 12).
// ---------------------------------------------------------------------------
#define HO_WG   0
#define HO_IPW  2048
#define HO_OW   6144
#define HO_M1W  10240
#define HO_M2W  12288
#define HO_BG   12608
#define HO_GG   12672
#define HO_BEG  12736
#define HO_IPB  12800
#define HO_OB   12864
#define HO_M1B  12928
#define HO_M2B  12960
#define HO_GS   12976
#define HO_A    13008
#define HO_VV   13072
#define HO_AO   13136
#define HO_HH   13200
#define HO_PP   13232
#define HO_RED  13488
#define HEAD_SMEM ((13492) * 4)

__global__ __launch_bounds__(256) void head_kernel(
    const float* __restrict__ wg,  const float* __restrict__ bg,
    const float* __restrict__ gg,  const float* __restrict__ beg,
    const float* __restrict__ ipw, const float* __restrict__ ipb,
    const float* __restrict__ ow,  const float* __restrict__ ob,
    const float* __restrict__ m1w, const float* __restrict__ m1b,
    const float* __restrict__ m2w, const float* __restrict__ m2b,
    float* __restrict__ out)
{
    extern __shared__ __align__(16) float sh[];
    int b    = blockIdx.x;
    int tid  = threadIdx.x;
    int t    = tid & 63;
    int q    = tid >> 6;
    int lane = tid & 31;
    int wid  = tid >> 5;

    float gsv = 0.f;
    if (tid < 32) {
        const float4* gp = reinterpret_cast<const float4*>(
            &g_part[(b * C2 + tid) * 8]);
        float4 p0 = gp[0], p1 = gp[1];
        gsv = (p0.x + p0.y + p0.z + p0.w + p1.x + p1.y + p1.z + p1.w)
              * (1.0f / 4096.0f);
    }

#define CP4(off, src, n4)                                                   \
    for (int i = tid; i < (n4); i += 256)                                   \
        reinterpret_cast<float4*>(sh + (off))[i] =                          \
            reinterpret_cast<const float4*>(src)[i];
    CP4(HO_WG,  wg,            512)
    CP4(HO_IPW, ipw + 128 * 64, 1024)
    CP4(HO_OW,  ow,            1024)
    CP4(HO_M1W, m1w,           512)
    CP4(HO_M2W, m2w,           80)
    CP4(HO_BG,  bg,  16)
    CP4(HO_GG,  gg,  16)
    CP4(HO_BEG, beg, 16)
    CP4(HO_IPB, ipb + 128, 16)
    CP4(HO_OB,  ob,  16)
    CP4(HO_M1B, m1b, 8)
#undef CP4
    if (tid < 10) sh[HO_M2B + tid] = m2b[tid];
    if (tid < 32) sh[HO_GS + tid] = gsv;
    __syncthreads();

    float* pp = sh + HO_PP;

    {
        float s = 0.f;
#pragma unroll
        for (int i = 0; i < 8; i++) {
            int e = q * 8 + i;
            s += sh[HO_GS + e] * sh[HO_WG + e * 64 + t];
        }
        pp[q * 64 + t] = s;
    }
    __syncthreads();
    float pre = 0.f;
    if (tid < 64) {
        pre = pp[t] + pp[64 + t] + pp[128 + t] + pp[192 + t] + sh[HO_BG + t];
        pre = fmaxf(pre, 0.f);
    }
    if (tid < 64) {
        float s = pre;
#pragma unroll
        for (int o = 16; o > 0; o >>= 1) s += __shfl_xor_sync(0xffffffffu, s, o);
        if (lane == 0) sh[HO_RED + wid] = s;
    }
    __syncthreads();
    float mean = (sh[HO_RED] + sh[HO_RED + 1]) * (1.0f / 64.0f);
    if (tid < 64) {
        float d = pre - mean;
        float s = d * d;
#pragma unroll
        for (int o = 16; o > 0; o >>= 1) s += __shfl_xor_sync(0xffffffffu, s, o);
        if (lane == 0) sh[HO_RED + 2 + wid] = s;
    }
    __syncthreads();
    if (tid < 64) {
        float var = (sh[HO_RED + 2] + sh[HO_RED + 3]) * (1.0f / 64.0f);
        sh[HO_A + t] = (pre - mean) * rsqrtf(var + 1e-5f) * sh[HO_GG + t]
                       + sh[HO_BEG + t];
    }
    __syncthreads();

    {
        float s = 0.f;
#pragma unroll
        for (int i = 0; i < 16; i++) {
            int e = q * 16 + i;
            s += sh[HO_A + e] * sh[HO_IPW + t * 64 + e];
        }
        pp[q * 64 + t] = s;
    }
    __syncthreads();
    if (tid < 64)
        sh[HO_VV + t] = pp[t] + pp[64 + t] + pp[128 + t] + pp[192 + t]
                        + sh[HO_IPB + t];
    __syncthreads();

    {
        float s = 0.f;
#pragma unroll
        for (int i = 0; i < 16; i++) {
            int j = q * 16 + i;
            s += sh[HO_VV + j] * sh[HO_OW + t * 64 + j];
        }
        pp[q * 64 + t] = s;
    }
    __syncthreads();
    if (tid < 64)
        sh[HO_AO + t] = pp[t] + pp[64 + t] + pp[128 + t] + pp[192 + t]
                        + sh[HO_OB + t];
    __syncthreads();

    {
        int t32 = tid & 31, q2 = wid;
        float s = 0.f;
#pragma unroll
        for (int i = 0; i < 8; i++) {
            int e = q2 * 8 + i;
            s += sh[HO_AO + e] * sh[HO_M1W + e * 32 + t32];
        }
        pp[q2 * 32 + t32] = s;
    }
    __syncthreads();
    if (tid < 32) {
        float s = sh[HO_M1B + tid];
#pragma unroll
        for (int g2 = 0; g2 < 8; g2++) s += pp[g2 * 32 + tid];
        sh[HO_HH + tid] = fmaxf(s, 0.f);
    }
    __syncthreads();

    if (tid < 10) {
        float o = sh[HO_M2B + tid];
#pragma unroll
        for (int m = 0; m < 32; m++)
            o += sh[HO_HH + m] * sh[HO_M2W + m * 10 + tid];
        out[b * 10 + tid] = o;
    }
}

// ---------------------------------------------------------------------------
extern "C" void kernel_launch(void* const* d_in, const int* in_sizes, int n_in,
                              void* d_out, int out_size)
{
    const float* x    = (const float*)d_in[0];
    const float* c1w  = (const float*)d_in[6];
    const float* c1b  = (const float*)d_in[7];
    const float* c2w  = (const float*)d_in[8];
    const float* c2b  = (const float*)d_in[9];
    const float* wg   = (const float*)d_in[10];
    const float* bg   = (const float*)d_in[11];
    const float* gg   = (const float*)d_in[12];
    const float* beg  = (const float*)d_in[13];
    const float* ipw  = (const float*)d_in[14];
    const float* ipb  = (const float*)d_in[15];
    const float* ow   = (const float*)d_in[16];
    const float* ob   = (const float*)d_in[17];
    const float* m1w  = (const float*)d_in[18];
    const float* m1b  = (const float*)d_in[19];
    const float* m2w  = (const float*)d_in[20];
    const float* m2b  = (const float*)d_in[21];
    float* out = (float*)d_out;

    cudaFuncSetAttribute(fused_conv_kernel,
                         cudaFuncAttributeMaxDynamicSharedMemorySize, FU_SMEM);
    cudaFuncSetAttribute(head_kernel,
                         cudaFuncAttributeMaxDynamicSharedMemorySize, HEAD_SMEM);

    dim3 g1(8, B_);
    fused_conv_kernel<<<g1, 256, FU_SMEM>>>(x, c1w, c1b, c2w, c2b);

    head_kernel<<<B_, 256, HEAD_SMEM>>>(wg, bg, gg, beg, ipw, ipb, ow, ob,
                                        m1w, m1b, m2w, m2b, out);
}